// round 2
// baseline (speedup 1.0000x reference)
#include <cuda_runtime.h>
#include <math.h>

#define B_   32
#define NF_  128
#define FLAT_ 784
#define HID2_ 392
#define EO_  64
#define FIN_ 8192
#define FHID_ 4096
#define OUT_ 53

// ---------------- scratch (static device allocations) ----------------
__device__ float g_a1[32 * 32 * 112 * 112];   // conv1 out (pooled)
__device__ float g_a2[32 * 64 * 56 * 56];     // conv2 out
__device__ float g_f [32 * 128 * 28 * 28];    // conv3 out == f [B][NF][784]
__device__ float g_lg[32 * 128];              // attention logits
__device__ float g_at[32 * 128];              // attention softmax
__device__ float g_h1[32 * 128 * 784];
__device__ float g_h2[32 * 128 * 392];
__device__ float g_e [32 * 8192];
__device__ float g_g1[32 * 8192];
__device__ float g_g2[32 * 4096];

// ---------------- packed f32x2 helpers ----------------
__device__ __forceinline__ unsigned long long pk2(float a, float b) {
    unsigned long long r;
    asm("mov.b64 %0, {%1,%2};" : "=l"(r) : "f"(a), "f"(b));
    return r;
}
__device__ __forceinline__ void fma2(unsigned long long& d, unsigned long long a, unsigned long long b) {
    asm("fma.rn.f32x2 %0, %1, %2, %0;" : "+l"(d) : "l"(a), "l"(b));
}
__device__ __forceinline__ float2 upk(unsigned long long v) {
    float2 r;
    asm("mov.b64 {%0,%1}, %2;" : "=f"(r.x), "=f"(r.y) : "l"(v));
    return r;
}

// ---------------- fused conv3x3(SAME)+bias+relu+maxpool2, f32x2 over co-pairs ----------------
// Each thread: 2x2 pooled outputs (4x4 pre-pool, 6x6 input halo) for 2 adjacent co.
template<int CI>
__global__ __launch_bounds__(224)
void conv_pool2_kernel(const float* __restrict__ in, const float* __restrict__ w,
                       const float* __restrict__ bias, float* __restrict__ out,
                       int H, int W, int CO)
{
    const int HP = H >> 1, WP = W >> 1;
    const int TX = WP >> 1, TY = HP >> 1;      // thread-tile grid (each 2x2 pooled)
    __shared__ unsigned long long sw[CI * 9];  // weights packed over co pair
    const int tid = threadIdx.x;
    const int co0 = blockIdx.y * 2;
    const int b   = blockIdx.z;

    for (int i = tid; i < CI * 9; i += 224)
        sw[i] = pk2(w[(long)co0 * CI * 9 + i], w[(long)(co0 + 1) * CI * 9 + i]);
    __syncthreads();

    const int t = blockIdx.x * 224 + tid;
    if (t >= TX * TY) return;
    const int ty = t / TX, tx = t % TX;
    const int y0 = 4 * ty - 1, x0 = 4 * tx - 1;   // input halo top-left

    unsigned long long acc[16];
#pragma unroll
    for (int i = 0; i < 16; i++) acc[i] = 0ull;

    const float* ip = in + ((long)b * CI) * H * W;
    for (int ci = 0; ci < CI; ci++, ip += (long)H * W) {
        unsigned long long vv[6][6];
#pragma unroll
        for (int r = 0; r < 6; r++) {
            const int yy = y0 + r;
            const bool yok = (yy >= 0) && (yy < H);
#pragma unroll
            for (int c = 0; c < 6; c++) {
                const int xx = x0 + c;
                float v = (yok && xx >= 0 && xx < W) ? __ldg(ip + (long)yy * W + xx) : 0.f;
                vv[r][c] = pk2(v, v);
            }
        }
        const unsigned long long* swc = sw + ci * 9;
#pragma unroll
        for (int ky = 0; ky < 3; ky++) {
#pragma unroll
            for (int kx = 0; kx < 3; kx++) {
                const unsigned long long wp = swc[ky * 3 + kx];
#pragma unroll
                for (int oy = 0; oy < 4; oy++)
#pragma unroll
                    for (int ox = 0; ox < 4; ox++)
                        fma2(acc[oy * 4 + ox], vv[oy + ky][ox + kx], wp);
            }
        }
    }

    const float b0 = bias[co0], b1 = bias[co0 + 1];
#pragma unroll
    for (int py = 0; py < 2; py++) {
#pragma unroll
        for (int px = 0; px < 2; px++) {
            const float2 m00 = upk(acc[(2 * py) * 4 + 2 * px]);
            const float2 m01 = upk(acc[(2 * py) * 4 + 2 * px + 1]);
            const float2 m10 = upk(acc[(2 * py + 1) * 4 + 2 * px]);
            const float2 m11 = upk(acc[(2 * py + 1) * 4 + 2 * px + 1]);
            float v0 = fmaxf(fmaxf(m00.x, m01.x), fmaxf(m10.x, m11.x)) + b0;
            float v1 = fmaxf(fmaxf(m00.y, m01.y), fmaxf(m10.y, m11.y)) + b1;
            v0 = fmaxf(v0, 0.f); v1 = fmaxf(v1, 0.f);
            const int ppy = 2 * ty + py, ppx = 2 * tx + px;
            out[(((long)b * CO + co0    ) * HP + ppy) * WP + ppx] = v0;
            out[(((long)b * CO + co0 + 1) * HP + ppy) * WP + ppx] = v1;
        }
    }
}

// ---------------- attention ----------------
__global__ void attn_logits_kernel(const float* __restrict__ f, const float* __restrict__ wa,
                                   const float* __restrict__ ba, float* __restrict__ logits)
{
    const int n = blockIdx.x, b = blockIdx.y;
    const float* fp = f + ((long)b * NF_ + n) * FLAT_;
    float s = 0.f;
    for (int k = threadIdx.x; k < FLAT_; k += 128)
        s += fp[k] * wa[k];
    __shared__ float red[128];
    red[threadIdx.x] = s;
    __syncthreads();
    for (int off = 64; off > 0; off >>= 1) {
        if (threadIdx.x < off) red[threadIdx.x] += red[threadIdx.x + off];
        __syncthreads();
    }
    if (threadIdx.x == 0) logits[b * NF_ + n] = red[0] + ba[0];
}

__global__ void attn_softmax_kernel(const float* __restrict__ logits, float* __restrict__ att)
{
    __shared__ float sh[128];
    const int b = blockIdx.x, n = threadIdx.x;
    const float v = logits[b * NF_ + n];
    sh[n] = v;
    __syncthreads();
    for (int off = 64; off > 0; off >>= 1) {
        if (n < off) sh[n] = fmaxf(sh[n], sh[n + off]);
        __syncthreads();
    }
    const float mx = sh[0];
    __syncthreads();
    const float e = expf(v - mx);
    sh[n] = e;
    __syncthreads();
    for (int off = 64; off > 0; off >>= 1) {
        if (n < off) sh[n] += sh[n + off];
        __syncthreads();
    }
    att[b * NF_ + n] = e / sh[0];
}

// ---------------- init output with bias (for atomic-accumulate GEMMs) ----------------
__global__ void init_bias_kernel(float* __restrict__ C, const float* __restrict__ bias, int N, int M)
{
    const int i = blockIdx.x * blockDim.x + threadIdx.x;
    if (i < M * N) C[i] = bias[i % N];
}

// ---------------- skinny batched GEMM: C[32,N] = op(A[32,K]) @ W[K,N] ----------------
// 128 threads: 4 b-groups (8 rows = 4 row-pairs) x 32 j-threads (4 cols each).
// f32x2 paired over batch rows: A pairs load directly from smem, W scalars duplicated.
template<bool ARELU, bool ASCALE, bool ATOMIC, bool ORELU>
__global__ __launch_bounds__(128)
void gemm_m32_kernel(const float* __restrict__ A, long strideA_n, long lda,
                     const float* __restrict__ scale,           // att base; s(b)=scale[b*128+n]
                     const float* __restrict__ W, long strideW_n,
                     const float* __restrict__ bias, long strideBias_n,
                     float* __restrict__ C, long strideC_n, long ldc,
                     int K, int N)
{
    const int n   = blockIdx.y;
    const int j0  = blockIdx.x * 128;
    const int tid = threadIdx.x;
    const int jt  = tid & 31;
    const int bg  = tid >> 5;

    A += (long)n * strideA_n;
    W += (long)n * strideW_n;
    C += (long)n * strideC_n;

    const int kchunks = (K + 31) >> 5;
    const int per = (kchunks + gridDim.z - 1) / gridDim.z;
    const int c0 = blockIdx.z * per;
    const int c1 = min(kchunks, c0 + per);

    __shared__ float Ast[32][36];    // [k][b]; rows 144B => 16B-aligned pair reads
    __shared__ float Ws[32][128];
    __shared__ float ssc[32];

    if (ASCALE) {
        if (tid < 32) ssc[tid] = scale[(long)tid * NF_ + n];
    }

    const bool vecN = ((N & 3) == 0);

    unsigned long long acc[4][4];    // [row-pair][col]
#pragma unroll
    for (int r = 0; r < 4; r++)
#pragma unroll
        for (int c = 0; c < 4; c++) acc[r][c] = 0ull;

    for (int cc = c0; cc < c1; cc++) {
        const int k0 = cc << 5;
        __syncthreads();
        // A tile -> Ast[k][b]
#pragma unroll
        for (int i = 0; i < 8; i++) {
            const int b  = bg + i * 4;
            const int k  = jt;
            const int kk = k0 + k;
            float v = (kk < K) ? __ldg(A + (long)b * lda + kk) : 0.f;
            if (ARELU)  v = fmaxf(v, 0.f);
            if (ASCALE) v *= ssc[b];
            Ast[k][b] = v;
        }
        // W tile -> Ws (float4 fast path when N % 4 == 0)
        if (vecN) {
#pragma unroll
            for (int i = 0; i < 8; i++) {
                const int f4 = i * 128 + tid;         // 0..1023 float4 slots
                const int row = f4 >> 5, c4 = (f4 & 31) * 4;
                const int kk = k0 + row, jj = j0 + c4;
                float4 v = make_float4(0.f, 0.f, 0.f, 0.f);
                if (kk < K && jj + 3 < N)
                    v = __ldg((const float4*)(W + (long)kk * N + jj));
                else if (kk < K) {
                    if (jj     < N) v.x = __ldg(W + (long)kk * N + jj);
                    if (jj + 1 < N) v.y = __ldg(W + (long)kk * N + jj + 1);
                    if (jj + 2 < N) v.z = __ldg(W + (long)kk * N + jj + 2);
                    if (jj + 3 < N) v.w = __ldg(W + (long)kk * N + jj + 3);
                }
                *(float4*)&Ws[row][c4] = v;
            }
        } else {
#pragma unroll
            for (int i = 0; i < 32; i++) {
                const int kk = k0 + i;
                const int jj = j0 + tid;
                Ws[i][tid] = (kk < K && jj < N) ? __ldg(W + (long)kk * N + jj) : 0.f;
            }
        }
        __syncthreads();
#pragma unroll 8
        for (int k = 0; k < 32; k++) {
            const float4 w4 = *(const float4*)&Ws[k][jt * 4];
            unsigned long long wd0 = pk2(w4.x, w4.x);
            unsigned long long wd1 = pk2(w4.y, w4.y);
            unsigned long long wd2 = pk2(w4.z, w4.z);
            unsigned long long wd3 = pk2(w4.w, w4.w);
            const unsigned long long* ap = (const unsigned long long*)&Ast[k][bg * 8];
            unsigned long long a0 = ap[0], a1 = ap[1], a2 = ap[2], a3 = ap[3];
#pragma unroll
            for (int r = 0; r < 4; r++) {
                const unsigned long long av = (r == 0) ? a0 : (r == 1) ? a1 : (r == 2) ? a2 : a3;
                fma2(acc[r][0], av, wd0);
                fma2(acc[r][1], av, wd1);
                fma2(acc[r][2], av, wd2);
                fma2(acc[r][3], av, wd3);
            }
        }
    }

    if (ATOMIC) {
#pragma unroll
        for (int r = 0; r < 4; r++) {
            const int b = bg * 8 + 2 * r;
#pragma unroll
            for (int c = 0; c < 4; c++) {
                const int j = j0 + jt * 4 + c;
                if (j < N) {
                    const float2 v = upk(acc[r][c]);
                    atomicAdd(&C[(long)b * ldc + j], v.x);
                    atomicAdd(&C[(long)(b + 1) * ldc + j], v.y);
                }
            }
        }
    } else {
        const float* bn = bias + (long)n * strideBias_n;
#pragma unroll
        for (int r = 0; r < 4; r++) {
            const int b = bg * 8 + 2 * r;
#pragma unroll
            for (int c = 0; c < 4; c++) {
                const int j = j0 + jt * 4 + c;
                if (j < N) {
                    const float2 a = upk(acc[r][c]);
                    float v0 = a.x + bn[j];
                    float v1 = a.y + bn[j];
                    if (ORELU) { v0 = fmaxf(v0, 0.f); v1 = fmaxf(v1, 0.f); }
                    C[(long)b * ldc + j] = v0;
                    C[(long)(b + 1) * ldc + j] = v1;
                }
            }
        }
    }
}

// ---------------- launch ----------------
extern "C" void kernel_launch(void* const* d_in, const int* in_sizes, int n_in,
                              void* d_out, int out_size)
{
    const float* x   = (const float*)d_in[0];
    const float* cw1 = (const float*)d_in[1];
    const float* cb1 = (const float*)d_in[2];
    const float* cw2 = (const float*)d_in[3];
    const float* cb2 = (const float*)d_in[4];
    const float* cw3 = (const float*)d_in[5];
    const float* cb3 = (const float*)d_in[6];
    const float* wa  = (const float*)d_in[7];
    const float* ba  = (const float*)d_in[8];
    const float* ew1 = (const float*)d_in[9];
    const float* eb1 = (const float*)d_in[10];
    const float* ew2 = (const float*)d_in[11];
    const float* eb2 = (const float*)d_in[12];
    const float* ew3 = (const float*)d_in[13];
    const float* eb3 = (const float*)d_in[14];
    const float* fw1 = (const float*)d_in[15];
    const float* fb1 = (const float*)d_in[16];
    const float* fw2 = (const float*)d_in[17];
    const float* fb2 = (const float*)d_in[18];
    const float* fw3 = (const float*)d_in[19];
    const float* fb3 = (const float*)d_in[20];
    float* out = (float*)d_out;

    float *a1, *a2, *f, *lg, *att, *h1, *h2, *e, *g1, *g2;
    cudaGetSymbolAddress((void**)&a1,  g_a1);
    cudaGetSymbolAddress((void**)&a2,  g_a2);
    cudaGetSymbolAddress((void**)&f,   g_f);
    cudaGetSymbolAddress((void**)&lg,  g_lg);
    cudaGetSymbolAddress((void**)&att, g_at);
    cudaGetSymbolAddress((void**)&h1,  g_h1);
    cudaGetSymbolAddress((void**)&h2,  g_h2);
    cudaGetSymbolAddress((void**)&e,   g_e);
    cudaGetSymbolAddress((void**)&g1,  g_g1);
    cudaGetSymbolAddress((void**)&g2,  g_g2);

    // CNN stem (f32x2 paired over co; thread = 2x2 pooled outputs)
    // tiles: conv1 56x56=3136 (=14*224), conv2 28x28=784, conv3 14x14=196
    conv_pool2_kernel<3> <<<dim3(14, 16, 32), 224>>>(x,  cw1, cb1, a1, 224, 224, 32);
    conv_pool2_kernel<32><<<dim3(4, 32, 32), 224>>>(a1, cw2, cb2, a2, 112, 112, 64);
    conv_pool2_kernel<64><<<dim3(1, 64, 32), 224>>>(a2, cw3, cb3, f,  56,  56,  128);

    // attention over feature maps
    attn_logits_kernel<<<dim3(128, 32), 128>>>(f, wa, ba, lg);
    attn_softmax_kernel<<<32, 128>>>(lg, att);

    // experts (att-scale fused into E1 A-load; bias+relu fused into stores)
    gemm_m32_kernel<false, true, false, true><<<dim3(7, 128, 1), 128>>>(
        f, 784L, 128L * 784, att, ew1, 784L * 784, eb1, 784L, h1, 784L, 128L * 784, 784, 784);
    gemm_m32_kernel<false, false, false, true><<<dim3(4, 128, 1), 128>>>(
        h1, 784L, 128L * 784, nullptr, ew2, 784L * 392, eb2, 392L, h2, 392L, 128L * 392, 784, 392);
    gemm_m32_kernel<false, false, false, true><<<dim3(1, 128, 1), 128>>>(
        h2, 392L, 128L * 392, nullptr, ew3, 392L * 64, eb3, 64L, e, 64L, 8192L, 392, 64);

    // head: K-split atomics, bias pre-init, relu deferred to consumer A-load
    init_bias_kernel<<<1024, 256>>>(g1, fb1, FIN_, B_);
    gemm_m32_kernel<false, false, true, false><<<dim3(64, 1, 8), 128>>>(
        e, 0L, 8192L, nullptr, fw1, 0L, nullptr, 0L, g1, 0L, 8192L, 8192, 8192);

    init_bias_kernel<<<512, 256>>>(g2, fb2, FHID_, B_);
    gemm_m32_kernel<true, false, true, false><<<dim3(32, 1, 8), 128>>>(
        g1, 0L, 8192L, nullptr, fw2, 0L, nullptr, 0L, g2, 0L, 4096L, 8192, 4096);

    init_bias_kernel<<<7, 256>>>(out, fb3, OUT_, B_);
    gemm_m32_kernel<true, false, true, false><<<dim3(1, 1, 16), 128>>>(
        g2, 0L, 4096L, nullptr, fw3, 0L, nullptr, 0L, out, 0L, 53L, 4096, 53);
}

// round 10
// speedup vs baseline: 1.5848x; 1.5848x over previous
#include <cuda_runtime.h>
#include <math.h>

#define B_   32
#define NF_  128
#define FLAT_ 784
#define HID2_ 392
#define EO_  64
#define FIN_ 8192
#define FHID_ 4096
#define OUT_ 53

// ---------------- scratch (static device allocations) ----------------
__device__ float g_a1[32 * 32 * 112 * 112];   // conv1 out (pooled)
__device__ float g_a2[32 * 64 * 56 * 56];     // conv2 out
__device__ float g_f [32 * 128 * 28 * 28];    // conv3 out == f [B][NF][784]
__device__ float g_lg[32 * 128];              // attention logits
__device__ float g_at[32 * 128];              // attention softmax
__device__ float g_h1[32 * 128 * 784];
__device__ float g_h2[32 * 128 * 392];
__device__ float g_e [32 * 8192];
__device__ float g_g1[32 * 8192];
__device__ float g_g2[32 * 4096];
__device__ unsigned g_wt2[9 * 32 * 64];       // conv2 weights [tap][ci][co] tf32
__device__ unsigned g_wt3[9 * 64 * 128];      // conv3 weights [tap][ci][co] tf32

// ---------------- tf32 helpers ----------------
__device__ __forceinline__ unsigned tf32_of(float x) {
    unsigned r;
    asm("cvt.rna.tf32.f32 %0, %1;" : "=r"(r) : "f"(x));
    return r;
}
__device__ __forceinline__ void mma_tf32(float* c, const unsigned* a, const unsigned* b) {
    asm("mma.sync.aligned.m16n8k8.row.col.f32.tf32.tf32.f32 "
        "{%0,%1,%2,%3}, {%4,%5,%6,%7}, {%8,%9}, {%0,%1,%2,%3};"
        : "+f"(c[0]), "+f"(c[1]), "+f"(c[2]), "+f"(c[3])
        : "r"(a[0]), "r"(a[1]), "r"(a[2]), "r"(a[3]), "r"(b[0]), "r"(b[1]));
}

// ---------------- conv1: fused conv3x3(SAME)+bias+relu+maxpool2 (fp32, CI=3) ----------------
template<int CI, int CO_T>
__global__ __launch_bounds__(256)
void conv_pool_kernel(const float* __restrict__ in, const float* __restrict__ w,
                      const float* __restrict__ bias, float* __restrict__ out,
                      int H, int W, int CO)
{
    __shared__ float sw[CO_T * CI * 9];
    const int tid = threadIdx.x;
    const int co0 = blockIdx.y * CO_T;
    const int b   = blockIdx.z;

    for (int i = tid; i < CO_T * CI * 9; i += blockDim.x)
        sw[i] = w[(long)co0 * CI * 9 + i];
    __syncthreads();

    const int HP = H >> 1, WP = W >> 1;
    const int p = blockIdx.x * blockDim.x + tid;
    if (p >= HP * WP) return;
    const int py = p / WP, px = p % WP;
    const int y0 = 2 * py, x0 = 2 * px;

    float acc[CO_T][4];
#pragma unroll
    for (int t = 0; t < CO_T; t++)
        acc[t][0] = acc[t][1] = acc[t][2] = acc[t][3] = 0.f;

    for (int ci = 0; ci < CI; ci++) {
        const float* ip = in + ((long)(b * CI + ci)) * H * W;
        float v[4][4];
#pragma unroll
        for (int r = 0; r < 4; r++) {
            const int yy = y0 - 1 + r;
            const bool yok = (yy >= 0) && (yy < H);
#pragma unroll
            for (int c = 0; c < 4; c++) {
                const int xx = x0 - 1 + c;
                const bool ok = yok && (xx >= 0) && (xx < W);
                v[r][c] = ok ? __ldg(ip + (long)yy * W + xx) : 0.f;
            }
        }
        const float* swc = sw + ci * 9;
#pragma unroll
        for (int t = 0; t < CO_T; t++) {
            const float* wt = swc + t * CI * 9;
#pragma unroll
            for (int ky = 0; ky < 3; ky++)
#pragma unroll
                for (int kx = 0; kx < 3; kx++) {
                    const float wv = wt[ky * 3 + kx];
                    acc[t][0] = fmaf(v[ky    ][kx    ], wv, acc[t][0]);
                    acc[t][1] = fmaf(v[ky    ][kx + 1], wv, acc[t][1]);
                    acc[t][2] = fmaf(v[ky + 1][kx    ], wv, acc[t][2]);
                    acc[t][3] = fmaf(v[ky + 1][kx + 1], wv, acc[t][3]);
                }
        }
    }
#pragma unroll
    for (int t = 0; t < CO_T; t++) {
        const float bv = bias[co0 + t];
        float m = fmaxf(fmaxf(acc[t][0], acc[t][1]), fmaxf(acc[t][2], acc[t][3])) + bv;
        m = fmaxf(m, 0.f);
        out[(((long)b * CO + co0 + t) * HP + py) * WP + px] = m;
    }
}

// ---------------- weight transpose: [co][ci][3][3] fp32 -> [tap][ci][co] tf32 ----------------
__global__ void wt_transpose_kernel(const float* __restrict__ w, unsigned* __restrict__ wt,
                                    int CI, int CO)
{
    const int idx = blockIdx.x * blockDim.x + threadIdx.x;
    const int total = CO * CI * 9;
    if (idx >= total) return;
    const int co = idx % CO;
    const int rest = idx / CO;
    const int ci = rest % CI;
    const int tap = rest / CI;
    wt[idx] = tf32_of(w[((long)co * CI + ci) * 9 + tap]);
}

// ---------------- conv2/3: implicit-GEMM tf32 conv+bias+relu+pool ----------------
// Block: 128 threads (4 warps over M). Tile: M=128 pre-pool pixels (16 wide x 8 high),
// N=64 output channels. Loops: ci-chunks of 32, then 9 taps; same input patch serves all taps.
__global__ __launch_bounds__(128)
void conv_tc_kernel(const float* __restrict__ in, const unsigned* __restrict__ wt,
                    const float* __restrict__ bias, float* __restrict__ out,
                    int H, int W, int CItot, int COtot, int coBlocks)
{
    const int tid  = threadIdx.x;
    const int warp = tid >> 5;
    const int lane = tid & 31;
    const int gr   = lane >> 2;
    const int gq   = lane & 3;
    const int b    = blockIdx.z / coBlocks;
    const int co0  = (blockIdx.z % coBlocks) * 64;
    const int x0   = blockIdx.x * 16;
    const int y0   = blockIdx.y * 8;
    const int HP = H >> 1, WP = W >> 1;

    __shared__ __align__(16) char raw[34048];
    unsigned* patchS = (unsigned*)raw;             // [ci][10][20]: ci*200 + r*20 + c (c<18 used)
    unsigned* WtS    = (unsigned*)(raw + 25600);   // [ci][65]
    float*    preS   = (float*)raw;                // [m][65] (epilogue, aliases patch/Wt)

    float acc[2][8][4];
#pragma unroll
    for (int mt = 0; mt < 2; mt++)
#pragma unroll
        for (int nt = 0; nt < 8; nt++)
#pragma unroll
            for (int i = 0; i < 4; i++) acc[mt][nt][i] = 0.f;

    for (int ci0 = 0; ci0 < CItot; ci0 += 32) {
        __syncthreads();
        // input patch: 32 ci x 10 rows x 18 cols, zero-padded (SAME)
        for (int idx = tid; idx < 32 * 180; idx += 128) {
            const int ci = idx / 180, rem = idx % 180;
            const int r = rem / 18, c = rem % 18;
            const int y = y0 - 1 + r, x = x0 - 1 + c;
            float v = 0.f;
            if (y >= 0 && y < H && x >= 0 && x < W)
                v = __ldg(in + ((long)(b * CItot + ci0 + ci) * H + y) * W + x);
            patchS[ci * 200 + r * 20 + c] = tf32_of(v);
        }
        for (int tap = 0; tap < 9; tap++) {
            __syncthreads();
            // weight tile for this tap: [32 ci][64 co], coalesced over co
#pragma unroll
            for (int i = 0; i < 16; i++) {
                const int idx = tid + i * 128;
                const int ci = idx >> 6, co = idx & 63;
                WtS[ci * 65 + co] =
                    __ldg(wt + ((long)tap * CItot + ci0 + ci) * COtot + co0 + co);
            }
            __syncthreads();
            const int ky = tap / 3, kx = tap % 3;
#pragma unroll
            for (int kb = 0; kb < 32; kb += 8) {
                unsigned a[2][4];
#pragma unroll
                for (int mt = 0; mt < 2; mt++) {
                    const unsigned* pb = patchS + (kb + gq) * 200 + (2 * warp + mt + ky) * 20 + kx;
                    a[mt][0] = pb[gr];
                    a[mt][1] = pb[gr + 8];
                    a[mt][2] = pb[4 * 200 + gr];
                    a[mt][3] = pb[4 * 200 + gr + 8];
                }
                unsigned bf[8][2];
#pragma unroll
                for (int nt = 0; nt < 8; nt++) {
                    bf[nt][0] = WtS[(kb + gq    ) * 65 + nt * 8 + gr];
                    bf[nt][1] = WtS[(kb + gq + 4) * 65 + nt * 8 + gr];
                }
#pragma unroll
                for (int mt = 0; mt < 2; mt++)
#pragma unroll
                    for (int nt = 0; nt < 8; nt++)
                        mma_tf32(acc[mt][nt], a[mt], bf[nt]);
            }
        }
    }

    // ---- epilogue: stash pre-pool conv results, then pool+bias+relu ----
    __syncthreads();
#pragma unroll
    for (int mt = 0; mt < 2; mt++)
#pragma unroll
        for (int nt = 0; nt < 8; nt++) {
            const int m0 = warp * 32 + mt * 16 + gr;
            const int cc = nt * 8 + 2 * gq;
            preS[m0 * 65 + cc]           = acc[mt][nt][0];
            preS[m0 * 65 + cc + 1]       = acc[mt][nt][1];
            preS[(m0 + 8) * 65 + cc]     = acc[mt][nt][2];
            preS[(m0 + 8) * 65 + cc + 1] = acc[mt][nt][3];
        }
    __syncthreads();
    for (int idx = tid; idx < 2048; idx += 128) {
        const int pp = idx & 31;       // pooled pixel 0..31 (8 wide x 4 high)
        const int co = idx >> 5;       // 0..63
        const int lx = (pp & 7) * 2, ly = (pp >> 3) * 2;
        const int m = ly * 16 + lx;
        float v = fmaxf(fmaxf(preS[m * 65 + co], preS[(m + 1) * 65 + co]),
                        fmaxf(preS[(m + 16) * 65 + co], preS[(m + 17) * 65 + co]));
        v = fmaxf(v + bias[co0 + co], 0.f);
        const int pxg = (x0 >> 1) + (pp & 7);
        const int pyg = (y0 >> 1) + (pp >> 3);
        if (pxg < WP && pyg < HP)
            out[((long)(b * COtot + co0 + co) * HP + pyg) * WP + pxg] = v;
    }
}

// ---------------- attention ----------------
__global__ void attn_logits_kernel(const float* __restrict__ f, const float* __restrict__ wa,
                                   const float* __restrict__ ba, float* __restrict__ logits)
{
    const int n = blockIdx.x, b = blockIdx.y;
    const float* fp = f + ((long)b * NF_ + n) * FLAT_;
    float s = 0.f;
    for (int k = threadIdx.x; k < FLAT_; k += 128)
        s += fp[k] * wa[k];
    __shared__ float red[128];
    red[threadIdx.x] = s;
    __syncthreads();
    for (int off = 64; off > 0; off >>= 1) {
        if (threadIdx.x < off) red[threadIdx.x] += red[threadIdx.x + off];
        __syncthreads();
    }
    if (threadIdx.x == 0) logits[b * NF_ + n] = red[0] + ba[0];
}

__global__ void attn_softmax_kernel(const float* __restrict__ logits, float* __restrict__ att)
{
    __shared__ float sh[128];
    const int b = blockIdx.x, n = threadIdx.x;
    const float v = logits[b * NF_ + n];
    sh[n] = v;
    __syncthreads();
    for (int off = 64; off > 0; off >>= 1) {
        if (n < off) sh[n] = fmaxf(sh[n], sh[n + off]);
        __syncthreads();
    }
    const float mx = sh[0];
    __syncthreads();
    const float e = expf(v - mx);
    sh[n] = e;
    __syncthreads();
    for (int off = 64; off > 0; off >>= 1) {
        if (n < off) sh[n] += sh[n + off];
        __syncthreads();
    }
    att[b * NF_ + n] = e / sh[0];
}

// ---------------- init output with bias (for atomic-accumulate GEMMs) ----------------
__global__ void init_bias_kernel(float* __restrict__ C, const float* __restrict__ bias, int N, int M)
{
    const int i = blockIdx.x * blockDim.x + threadIdx.x;
    if (i < M * N) C[i] = bias[i % N];
}

// ---------------- tensor-core skinny GEMM: C[32,N] = op(A[32,K]) @ W[K,N] ----------------
template<bool ARELU, bool ASCALE, bool ATOMIC, bool ORELU>
__global__ __launch_bounds__(128)
void gemm_tc_kernel(const float* __restrict__ A, long strideA_n, long lda,
                    const float* __restrict__ scale,
                    const float* __restrict__ W, long strideW_n,
                    const float* __restrict__ bias, long strideBias_n,
                    float* __restrict__ C, long strideC_n, long ldc,
                    int K, int N)
{
    const int n    = blockIdx.y;
    const int j0   = blockIdx.x * 64;
    const int tid  = threadIdx.x;
    const int warp = tid >> 5;
    const int lane = tid & 31;
    const int gr   = lane >> 2;
    const int gq   = lane & 3;

    A += (long)n * strideA_n;
    W += (long)n * strideW_n;
    C += (long)n * strideC_n;

    const int kchunks = (K + 31) >> 5;
    const int per = (kchunks + gridDim.z - 1) / gridDim.z;
    const int c0 = blockIdx.z * per;
    const int c1 = min(kchunks, c0 + per);

    __shared__ unsigned As[32][36];   // [m][k]
    __shared__ unsigned Ws[32][72];   // [k][n]
    __shared__ float ssc[32];

    if (ASCALE && tid < 32) ssc[tid] = scale[(long)tid * NF_ + n];

    const bool vecN = ((N & 3) == 0);   // float4 W loads only if rows are 16B-aligned

    float acc[4][4];
#pragma unroll
    for (int i = 0; i < 4; i++)
#pragma unroll
        for (int j = 0; j < 4; j++) acc[i][j] = 0.f;

    for (int cc = c0; cc < c1; cc++) {
        const int k0 = cc << 5;
        __syncthreads();
#pragma unroll
        for (int i = 0; i < 8; i++) {
            const int m  = warp + 4 * i;
            const int kk = k0 + lane;
            float v = (kk < K) ? __ldg(A + (long)m * lda + kk) : 0.f;
            if (ARELU)  v = fmaxf(v, 0.f);
            if (ASCALE) v *= ssc[m];
            As[m][lane] = tf32_of(v);
        }
#pragma unroll
        for (int i = 0; i < 4; i++) {
            const int slot = tid + 128 * i;
            const int kr = slot >> 4;
            const int c4 = (slot & 15) * 4;
            const int kk = k0 + kr;
            const int jj = j0 + c4;
            float4 v = make_float4(0.f, 0.f, 0.f, 0.f);
            if (kk < K) {
                if (vecN && jj + 3 < N) {
                    v = __ldg((const float4*)(W + (long)kk * N + jj));
                } else {
                    if (jj     < N) v.x = __ldg(W + (long)kk * N + jj);
                    if (jj + 1 < N) v.y = __ldg(W + (long)kk * N + jj + 1);
                    if (jj + 2 < N) v.z = __ldg(W + (long)kk * N + jj + 2);
                    if (jj + 3 < N) v.w = __ldg(W + (long)kk * N + jj + 3);
                }
            }
            Ws[kr][c4]     = tf32_of(v.x);
            Ws[kr][c4 + 1] = tf32_of(v.y);
            Ws[kr][c4 + 2] = tf32_of(v.z);
            Ws[kr][c4 + 3] = tf32_of(v.w);
        }
        __syncthreads();
#pragma unroll
        for (int ks = 0; ks < 4; ks++) {
            const int kb = ks * 8;
            unsigned a[2][4], bfr[2][2];
#pragma unroll
            for (int mt = 0; mt < 2; mt++) {
                a[mt][0] = As[mt * 16 + gr    ][kb + gq    ];
                a[mt][1] = As[mt * 16 + gr + 8][kb + gq    ];
                a[mt][2] = As[mt * 16 + gr    ][kb + gq + 4];
                a[mt][3] = As[mt * 16 + gr + 8][kb + gq + 4];
            }
#pragma unroll
            for (int nt = 0; nt < 2; nt++) {
                const int nc = warp * 16 + nt * 8 + gr;
                bfr[nt][0] = Ws[kb + gq    ][nc];
                bfr[nt][1] = Ws[kb + gq + 4][nc];
            }
#pragma unroll
            for (int mt = 0; mt < 2; mt++)
#pragma unroll
                for (int nt = 0; nt < 2; nt++)
                    mma_tf32(acc[mt * 2 + nt], a[mt], bfr[nt]);
        }
    }

#pragma unroll
    for (int mt = 0; mt < 2; mt++) {
#pragma unroll
        for (int nt = 0; nt < 2; nt++) {
            const float* ac = acc[mt * 2 + nt];
            const int row0 = mt * 16 + gr;
            const int col  = j0 + warp * 16 + nt * 8 + 2 * gq;
            if (ATOMIC) {
                if (col < N) {
                    atomicAdd(&C[(long)row0 * ldc + col], ac[0]);
                    atomicAdd(&C[(long)(row0 + 8) * ldc + col], ac[2]);
                }
                if (col + 1 < N) {
                    atomicAdd(&C[(long)row0 * ldc + col + 1], ac[1]);
                    atomicAdd(&C[(long)(row0 + 8) * ldc + col + 1], ac[3]);
                }
            } else {
                const float* bn = bias + (long)n * strideBias_n;
#pragma unroll
                for (int h = 0; h < 2; h++) {
                    const int j = col + h;
                    if (j < N) {
                        float v0 = ac[h]     + bn[j];
                        float v1 = ac[h + 2] + bn[j];
                        if (ORELU) { v0 = fmaxf(v0, 0.f); v1 = fmaxf(v1, 0.f); }
                        C[(long)row0 * ldc + j] = v0;
                        C[(long)(row0 + 8) * ldc + j] = v1;
                    }
                }
            }
        }
    }
}

// ---------------- launch ----------------
extern "C" void kernel_launch(void* const* d_in, const int* in_sizes, int n_in,
                              void* d_out, int out_size)
{
    const float* x   = (const float*)d_in[0];
    const float* cw1 = (const float*)d_in[1];
    const float* cb1 = (const float*)d_in[2];
    const float* cw2 = (const float*)d_in[3];
    const float* cb2 = (const float*)d_in[4];
    const float* cw3 = (const float*)d_in[5];
    const float* cb3 = (const float*)d_in[6];
    const float* wa  = (const float*)d_in[7];
    const float* ba  = (const float*)d_in[8];
    const float* ew1 = (const float*)d_in[9];
    const float* eb1 = (const float*)d_in[10];
    const float* ew2 = (const float*)d_in[11];
    const float* eb2 = (const float*)d_in[12];
    const float* ew3 = (const float*)d_in[13];
    const float* eb3 = (const float*)d_in[14];
    const float* fw1 = (const float*)d_in[15];
    const float* fb1 = (const float*)d_in[16];
    const float* fw2 = (const float*)d_in[17];
    const float* fb2 = (const float*)d_in[18];
    const float* fw3 = (const float*)d_in[19];
    const float* fb3 = (const float*)d_in[20];
    float* out = (float*)d_out;

    float *a1, *a2, *f, *lg, *att, *h1, *h2, *e, *g1, *g2;
    unsigned *wt2, *wt3;
    cudaGetSymbolAddress((void**)&a1,  g_a1);
    cudaGetSymbolAddress((void**)&a2,  g_a2);
    cudaGetSymbolAddress((void**)&f,   g_f);
    cudaGetSymbolAddress((void**)&lg,  g_lg);
    cudaGetSymbolAddress((void**)&att, g_at);
    cudaGetSymbolAddress((void**)&h1,  g_h1);
    cudaGetSymbolAddress((void**)&h2,  g_h2);
    cudaGetSymbolAddress((void**)&e,   g_e);
    cudaGetSymbolAddress((void**)&g1,  g_g1);
    cudaGetSymbolAddress((void**)&g2,  g_g2);
    cudaGetSymbolAddress((void**)&wt2, g_wt2);
    cudaGetSymbolAddress((void**)&wt3, g_wt3);

    // one-time-ish weight transposes (cheap; rerun every call for determinism)
    wt_transpose_kernel<<<72, 256>>>(cw2, wt2, 32, 64);
    wt_transpose_kernel<<<288, 256>>>(cw3, wt3, 64, 128);

    // CNN stem
    conv_pool_kernel<3, 8><<<dim3(49, 4, 32), 256>>>(x, cw1, cb1, a1, 224, 224, 32);
    conv_tc_kernel<<<dim3(7, 14, 32), 128>>>(a1, wt2, cb2, a2, 112, 112, 32, 64, 1);
    conv_tc_kernel<<<dim3(4, 7, 64), 128>>>(a2, wt3, cb3, f, 56, 56, 64, 128, 2);

    // attention over feature maps
    attn_logits_kernel<<<dim3(128, 32), 128>>>(f, wa, ba, lg);
    attn_softmax_kernel<<<32, 128>>>(lg, att);

    // experts (tf32 tensor cores; att-scale fused into E1 A-load; bias+relu on store)
    gemm_tc_kernel<false, true, false, true><<<dim3(13, 128, 1), 128>>>(
        f, 784L, 128L * 784, att, ew1, 784L * 784, eb1, 784L, h1, 784L, 128L * 784, 784, 784);
    gemm_tc_kernel<false, false, false, true><<<dim3(7, 128, 1), 128>>>(
        h1, 784L, 128L * 784, nullptr, ew2, 784L * 392, eb2, 392L, h2, 392L, 128L * 392, 784, 392);
    gemm_tc_kernel<false, false, false, true><<<dim3(1, 128, 1), 128>>>(
        h2, 392L, 128L * 392, nullptr, ew3, 392L * 64, eb3, 64L, e, 64L, 8192L, 392, 64);

    // head
    gemm_tc_kernel<false, false, false, true><<<dim3(128, 1, 1), 128>>>(
        e, 0L, 8192L, nullptr, fw1, 0L, fb1, 0L, g1, 0L, 8192L, 8192, 8192);

    init_bias_kernel<<<512, 256>>>(g2, fb2, FHID_, B_);
    gemm_tc_kernel<false, false, true, false><<<dim3(64, 1, 2), 128>>>(
        g1, 0L, 8192L, nullptr, fw2, 0L, nullptr, 0L, g2, 0L, 4096L, 8192, 4096);

    init_bias_kernel<<<7, 256>>>(out, fb3, OUT_, B_);
    gemm_tc_kernel<true, false, true, false><<<dim3(1, 1, 16), 128>>>(
        g2, 0L, 4096L, nullptr, fw3, 0L, nullptr, 0L, out, 0L, 53L, 4096, 53);
}

// round 11
// speedup vs baseline: 2.1975x; 1.3866x over previous
#include <cuda_runtime.h>
#include <math.h>

#define B_   32
#define NF_  128
#define FLAT_ 784
#define HID2_ 392
#define EO_  64
#define FIN_ 8192
#define FHID_ 4096
#define OUT_ 53

// ---------------- scratch (static device allocations) ----------------
__device__ float g_a1[32 * 32 * 112 * 112];   // conv1 out (pooled)
__device__ float g_a2[32 * 64 * 56 * 56];     // conv2 out
__device__ float g_f [32 * 128 * 28 * 28];    // conv3 out == f [B][NF][784]
__device__ float g_lg[32 * 128];
__device__ float g_at[32 * 128];
__device__ float g_h1[32 * 128 * 784];
__device__ float g_h2[32 * 128 * 392];
__device__ float g_e [32 * 8192];
__device__ float g_g1[32 * 8192];
__device__ float g_g2[32 * 4096];
// conv weights as bf16 pairs over ci: [tap][cip][co], hi & lo planes
__device__ unsigned g_wh2[9 * 16 * 64];
__device__ unsigned g_wl2[9 * 16 * 64];
__device__ unsigned g_wh3[9 * 32 * 128];
__device__ unsigned g_wl3[9 * 32 * 128];

// ---------------- bf16 split helpers ----------------
// pack (x -> lower half, y -> upper half); hi = rn(bf16), lo = rn(residual)
__device__ __forceinline__ void split2(float x, float y, unsigned& h, unsigned& l) {
    asm("cvt.rn.bf16x2.f32 %0, %1, %2;" : "=r"(h) : "f"(y), "f"(x));
    float rx = x - __uint_as_float(h << 16);
    float ry = y - __uint_as_float(h & 0xffff0000u);
    asm("cvt.rn.bf16x2.f32 %0, %1, %2;" : "=r"(l) : "f"(ry), "f"(rx));
}
__device__ __forceinline__ void mma_bf16(float* c, const unsigned* a, const unsigned* b) {
    asm("mma.sync.aligned.m16n8k16.row.col.f32.bf16.bf16.f32 "
        "{%0,%1,%2,%3}, {%4,%5,%6,%7}, {%8,%9}, {%0,%1,%2,%3};"
        : "+f"(c[0]), "+f"(c[1]), "+f"(c[2]), "+f"(c[3])
        : "r"(a[0]), "r"(a[1]), "r"(a[2]), "r"(a[3]), "r"(b[0]), "r"(b[1]));
}

// ---------------- conv1: fused conv3x3(SAME)+bias+relu+maxpool2 (fp32, CI=3) ----------------
template<int CI, int CO_T>
__global__ __launch_bounds__(256)
void conv_pool_kernel(const float* __restrict__ in, const float* __restrict__ w,
                      const float* __restrict__ bias, float* __restrict__ out,
                      int H, int W, int CO)
{
    __shared__ float sw[CO_T * CI * 9];
    const int tid = threadIdx.x;
    const int co0 = blockIdx.y * CO_T;
    const int b   = blockIdx.z;

    for (int i = tid; i < CO_T * CI * 9; i += blockDim.x)
        sw[i] = w[(long)co0 * CI * 9 + i];
    __syncthreads();

    const int HP = H >> 1, WP = W >> 1;
    const int p = blockIdx.x * blockDim.x + tid;
    if (p >= HP * WP) return;
    const int py = p / WP, px = p % WP;
    const int y0 = 2 * py, x0 = 2 * px;

    float acc[CO_T][4];
#pragma unroll
    for (int t = 0; t < CO_T; t++)
        acc[t][0] = acc[t][1] = acc[t][2] = acc[t][3] = 0.f;

    for (int ci = 0; ci < CI; ci++) {
        const float* ip = in + ((long)(b * CI + ci)) * H * W;
        float v[4][4];
#pragma unroll
        for (int r = 0; r < 4; r++) {
            const int yy = y0 - 1 + r;
            const bool yok = (yy >= 0) && (yy < H);
#pragma unroll
            for (int c = 0; c < 4; c++) {
                const int xx = x0 - 1 + c;
                const bool ok = yok && (xx >= 0) && (xx < W);
                v[r][c] = ok ? __ldg(ip + (long)yy * W + xx) : 0.f;
            }
        }
        const float* swc = sw + ci * 9;
#pragma unroll
        for (int t = 0; t < CO_T; t++) {
            const float* wt = swc + t * CI * 9;
#pragma unroll
            for (int ky = 0; ky < 3; ky++)
#pragma unroll
                for (int kx = 0; kx < 3; kx++) {
                    const float wv = wt[ky * 3 + kx];
                    acc[t][0] = fmaf(v[ky    ][kx    ], wv, acc[t][0]);
                    acc[t][1] = fmaf(v[ky    ][kx + 1], wv, acc[t][1]);
                    acc[t][2] = fmaf(v[ky + 1][kx    ], wv, acc[t][2]);
                    acc[t][3] = fmaf(v[ky + 1][kx + 1], wv, acc[t][3]);
                }
        }
    }
#pragma unroll
    for (int t = 0; t < CO_T; t++) {
        const float bv = bias[co0 + t];
        float m = fmaxf(fmaxf(acc[t][0], acc[t][1]), fmaxf(acc[t][2], acc[t][3])) + bv;
        m = fmaxf(m, 0.f);
        out[(((long)b * CO + co0 + t) * HP + py) * WP + px] = m;
    }
}

// ---------------- conv weight prep: [co][ci][3][3] fp32 -> hi/lo bf16 pairs [tap][cip][co] ----------------
__global__ void conv_wprep_kernel(const float* __restrict__ w,
                                  unsigned* __restrict__ whi, unsigned* __restrict__ wlo,
                                  int CI, int CO)
{
    const int idx = blockIdx.x * blockDim.x + threadIdx.x;
    const int CIP = CI >> 1;
    const int total = 9 * CIP * CO;
    if (idx >= total) return;
    const int co  = idx % CO;
    const int rest = idx / CO;
    const int cip = rest % CIP;
    const int tap = rest / CIP;
    const float v0 = w[((long)co * CI + 2 * cip)     * 9 + tap];
    const float v1 = w[((long)co * CI + 2 * cip + 1) * 9 + tap];
    unsigned h, l;
    split2(v0, v1, h, l);
    whi[idx] = h;
    wlo[idx] = l;
}

// ---------------- conv2/3: implicit-GEMM bf16 3-term, conv+bias+relu+pool ----------------
// 256 threads = 8 warps: warpM = warp>>1 (4 over M), warpN = warp&1 (2 over N).
// Tile: M=128 pre-pool pixels (16x x 8y), N=64 co. K loop: ci chunks of 32, 9 taps.
__global__ __launch_bounds__(256)
void conv_bf_kernel(const float* __restrict__ in,
                    const unsigned* __restrict__ whi, const unsigned* __restrict__ wlo,
                    const float* __restrict__ bias, float* __restrict__ out,
                    int H, int W, int CItot, int COtot, int coBlocks)
{
    const int tid   = threadIdx.x;
    const int warp  = tid >> 5;
    const int lane  = tid & 31;
    const int warpM = warp >> 1;
    const int warpN = warp & 1;
    const int gr    = lane >> 2;
    const int gq    = lane & 3;
    const int b     = blockIdx.z / coBlocks;
    const int co0   = (blockIdx.z % coBlocks) * 64;
    const int x0    = blockIdx.x * 16;
    const int y0    = blockIdx.y * 8;
    const int HP = H >> 1, WP = W >> 1;
    const int CIP = CItot >> 1;

    __shared__ __align__(16) unsigned char raw[34816];
    unsigned* pH  = (unsigned*)raw;                  // [cip16][10][20] stride 200
    unsigned* pL  = (unsigned*)(raw + 12800);
    unsigned* wHs = (unsigned*)(raw + 25600);        // [cip16][72]
    unsigned* wLs = (unsigned*)(raw + 30208);
    float*    preS = (float*)raw;                    // [128][65] epilogue alias

    float acc[2][4][4];
#pragma unroll
    for (int mt = 0; mt < 2; mt++)
#pragma unroll
        for (int nt = 0; nt < 4; nt++)
#pragma unroll
            for (int i = 0; i < 4; i++) acc[mt][nt][i] = 0.f;

    const long HW = (long)H * W;

    for (int ci0 = 0; ci0 < CItot; ci0 += 32) {
        __syncthreads();
        // patch: 16 ci-pairs x 10 rows x 18 cols (SAME zero pad), split hi/lo
        for (int idx = tid; idx < 2880; idx += 256) {
            const int cip = idx / 180, rem = idx % 180;
            const int r = rem / 18, c = rem % 18;
            const int y = y0 - 1 + r, x = x0 - 1 + c;
            float v0 = 0.f, v1 = 0.f;
            if (y >= 0 && y < H && x >= 0 && x < W) {
                const float* ip = in + ((long)(b * CItot + ci0 + 2 * cip) * H + y) * W + x;
                v0 = __ldg(ip);
                v1 = __ldg(ip + HW);
            }
            unsigned h, l;
            split2(v0, v1, h, l);
            pH[cip * 200 + r * 20 + c] = h;
            pL[cip * 200 + r * 20 + c] = l;
        }
        const int cip0 = ci0 >> 1;
        for (int tap = 0; tap < 9; tap++) {
            __syncthreads();
            // weight tile: 16 cip x 64 co, hi/lo
#pragma unroll
            for (int i = 0; i < 4; i++) {
                const int slot = tid + i * 256;
                const int cip = slot >> 6, co = slot & 63;
                const long src = ((long)tap * CIP + cip0 + cip) * COtot + co0 + co;
                wHs[cip * 72 + co] = __ldg(whi + src);
                wLs[cip * 72 + co] = __ldg(wlo + src);
            }
            __syncthreads();
            const int ky = tap / 3, kx = tap % 3;
#pragma unroll
            for (int kb = 0; kb < 2; kb++) {
                unsigned ah[2][4], al[2][4];
#pragma unroll
                for (int mt = 0; mt < 2; mt++) {
                    const int yrow = 2 * warpM + mt + ky;
                    const unsigned* bh_ = pH + (kb * 8 + gq) * 200 + yrow * 20 + kx;
                    const unsigned* bl_ = pL + (kb * 8 + gq) * 200 + yrow * 20 + kx;
                    ah[mt][0] = bh_[gr];       ah[mt][1] = bh_[gr + 8];
                    ah[mt][2] = bh_[800 + gr]; ah[mt][3] = bh_[800 + gr + 8];
                    al[mt][0] = bl_[gr];       al[mt][1] = bl_[gr + 8];
                    al[mt][2] = bl_[800 + gr]; al[mt][3] = bl_[800 + gr + 8];
                }
                unsigned bh[4][2], bl[4][2];
#pragma unroll
                for (int nt = 0; nt < 4; nt++) {
                    const int col = warpN * 32 + nt * 8 + gr;
                    bh[nt][0] = wHs[(kb * 8 + gq) * 72 + col];
                    bh[nt][1] = wHs[(kb * 8 + gq + 4) * 72 + col];
                    bl[nt][0] = wLs[(kb * 8 + gq) * 72 + col];
                    bl[nt][1] = wLs[(kb * 8 + gq + 4) * 72 + col];
                }
#pragma unroll
                for (int mt = 0; mt < 2; mt++)
#pragma unroll
                    for (int nt = 0; nt < 4; nt++) {
                        mma_bf16(acc[mt][nt], ah[mt], bh[nt]);
                        mma_bf16(acc[mt][nt], al[mt], bh[nt]);
                        mma_bf16(acc[mt][nt], ah[mt], bl[nt]);
                    }
            }
        }
    }

    // ---- epilogue: stash pre-pool, then pool+bias+relu ----
    __syncthreads();
#pragma unroll
    for (int mt = 0; mt < 2; mt++)
#pragma unroll
        for (int nt = 0; nt < 4; nt++) {
            const int m0 = (2 * warpM + mt) * 16;
            const int cc = warpN * 32 + nt * 8 + 2 * gq;
            const float* ac = acc[mt][nt];
            preS[(m0 + gr) * 65 + cc]         = ac[0];
            preS[(m0 + gr) * 65 + cc + 1]     = ac[1];
            preS[(m0 + gr + 8) * 65 + cc]     = ac[2];
            preS[(m0 + gr + 8) * 65 + cc + 1] = ac[3];
        }
    __syncthreads();
    for (int idx = tid; idx < 2048; idx += 256) {
        const int pp = idx & 31;     // pooled pixel (8 wide x 4 high)
        const int co = idx >> 5;
        const int lx = (pp & 7) * 2, ly = (pp >> 3) * 2;
        const int m = ly * 16 + lx;
        float v = fmaxf(fmaxf(preS[m * 65 + co], preS[(m + 1) * 65 + co]),
                        fmaxf(preS[(m + 16) * 65 + co], preS[(m + 17) * 65 + co]));
        v = fmaxf(v + bias[co0 + co], 0.f);
        const int pxg = (x0 >> 1) + (pp & 7);
        const int pyg = (y0 >> 1) + (pp >> 3);
        if (pxg < WP && pyg < HP)
            out[((long)(b * COtot + co0 + co) * HP + pyg) * WP + pxg] = v;
    }
}

// ---------------- attention ----------------
__global__ void attn_logits_kernel(const float* __restrict__ f, const float* __restrict__ wa,
                                   const float* __restrict__ ba, float* __restrict__ logits)
{
    const int n = blockIdx.x, b = blockIdx.y;
    const float* fp = f + ((long)b * NF_ + n) * FLAT_;
    float s = 0.f;
    for (int k = threadIdx.x; k < FLAT_; k += 128)
        s += fp[k] * wa[k];
    __shared__ float red[128];
    red[threadIdx.x] = s;
    __syncthreads();
    for (int off = 64; off > 0; off >>= 1) {
        if (threadIdx.x < off) red[threadIdx.x] += red[threadIdx.x + off];
        __syncthreads();
    }
    if (threadIdx.x == 0) logits[b * NF_ + n] = red[0] + ba[0];
}

__global__ void attn_softmax_kernel(const float* __restrict__ logits, float* __restrict__ att)
{
    __shared__ float sh[128];
    const int b = blockIdx.x, n = threadIdx.x;
    const float v = logits[b * NF_ + n];
    sh[n] = v;
    __syncthreads();
    for (int off = 64; off > 0; off >>= 1) {
        if (n < off) sh[n] = fmaxf(sh[n], sh[n + off]);
        __syncthreads();
    }
    const float mx = sh[0];
    __syncthreads();
    const float e = expf(v - mx);
    sh[n] = e;
    __syncthreads();
    for (int off = 64; off > 0; off >>= 1) {
        if (n < off) sh[n] += sh[n + off];
        __syncthreads();
    }
    att[b * NF_ + n] = e / sh[0];
}

// ---------------- init output with bias ----------------
__global__ void init_bias_kernel(float* __restrict__ C, const float* __restrict__ bias, int N, int M)
{
    const int i = blockIdx.x * blockDim.x + threadIdx.x;
    if (i < M * N) C[i] = bias[i % N];
}

// ---------------- bf16 3-term skinny GEMM: C[32,N] = op(A[32,K]) @ W[K,N] ----------------
// 128 threads = 4 warps over N (16 cols each). Tile M32 x N64 x K32 (2 x k16 steps).
template<bool ARELU, bool ASCALE, bool ATOMIC, bool ORELU>
__global__ __launch_bounds__(128)
void gemm_bf_kernel(const float* __restrict__ A, long strideA_n, long lda,
                    const float* __restrict__ scale,
                    const float* __restrict__ W, long strideW_n,
                    const float* __restrict__ bias, long strideBias_n,
                    float* __restrict__ C, long strideC_n, long ldc,
                    int K, int N)
{
    const int n    = blockIdx.y;
    const int j0   = blockIdx.x * 64;
    const int tid  = threadIdx.x;
    const int warp = tid >> 5;
    const int lane = tid & 31;
    const int gr   = lane >> 2;
    const int gq   = lane & 3;

    A += (long)n * strideA_n;
    W += (long)n * strideW_n;
    C += (long)n * strideC_n;

    const int kchunks = (K + 31) >> 5;
    const int per = (kchunks + gridDim.z - 1) / gridDim.z;
    const int c0 = blockIdx.z * per;
    const int c1 = min(kchunks, c0 + per);

    __shared__ unsigned Ah[32][18], Al[32][18];   // [m][kp]
    __shared__ unsigned Wh[64][18], Wl[64][18];   // [n][kp]
    __shared__ float ssc[32];

    if (ASCALE && tid < 32) ssc[tid] = scale[(long)tid * NF_ + n];

    const bool vecN = ((N & 3) == 0);

    float acc[2][2][4];
#pragma unroll
    for (int mt = 0; mt < 2; mt++)
#pragma unroll
        for (int nt = 0; nt < 2; nt++)
#pragma unroll
            for (int i = 0; i < 4; i++) acc[mt][nt][i] = 0.f;

    for (int cc = c0; cc < c1; cc++) {
        const int k0 = cc << 5;
        __syncthreads();
        // ---- A tile: 32 m x 16 kp ----
#pragma unroll
        for (int i = 0; i < 4; i++) {
            const int slot = tid + i * 128;
            const int m = slot >> 4, kp = slot & 15;
            const int kk = k0 + 2 * kp;
            float2 v = make_float2(0.f, 0.f);
            if (kk < K) v = *(const float2*)(A + (long)m * lda + kk);  // K even
            if (ARELU)  { v.x = fmaxf(v.x, 0.f); v.y = fmaxf(v.y, 0.f); }
            if (ASCALE) { const float s = ssc[m]; v.x *= s; v.y *= s; }
            unsigned h, l;
            split2(v.x, v.y, h, l);
            Ah[m][kp] = h;
            Al[m][kp] = l;
        }
        // ---- W tile: 64 n x 16 kp ----
        if (vecN) {
#pragma unroll
            for (int i = 0; i < 2; i++) {
                const int qs = tid + i * 128;       // 0..255 quad slots
                const int kp = qs >> 4, n4 = (qs & 15) * 4;
                const int kk = k0 + 2 * kp;
                const int jj = j0 + n4;
                float4 r0 = make_float4(0.f, 0.f, 0.f, 0.f);
                float4 r1 = r0;
                if (kk < K && jj + 3 < N) {
                    r0 = __ldg((const float4*)(W + (long)kk * N + jj));
                    r1 = __ldg((const float4*)(W + (long)(kk + 1) * N + jj));
                } else if (kk < K) {
                    const float* w0 = W + (long)kk * N;
                    const float* w1 = W + (long)(kk + 1) * N;
                    if (jj     < N) { r0.x = __ldg(w0 + jj);     r1.x = __ldg(w1 + jj); }
                    if (jj + 1 < N) { r0.y = __ldg(w0 + jj + 1); r1.y = __ldg(w1 + jj + 1); }
                    if (jj + 2 < N) { r0.z = __ldg(w0 + jj + 2); r1.z = __ldg(w1 + jj + 2); }
                    if (jj + 3 < N) { r0.w = __ldg(w0 + jj + 3); r1.w = __ldg(w1 + jj + 3); }
                }
                unsigned h, l;
                split2(r0.x, r1.x, h, l); Wh[n4    ][kp] = h; Wl[n4    ][kp] = l;
                split2(r0.y, r1.y, h, l); Wh[n4 + 1][kp] = h; Wl[n4 + 1][kp] = l;
                split2(r0.z, r1.z, h, l); Wh[n4 + 2][kp] = h; Wl[n4 + 2][kp] = l;
                split2(r0.w, r1.w, h, l); Wh[n4 + 3][kp] = h; Wl[n4 + 3][kp] = l;
            }
        } else {
#pragma unroll
            for (int i = 0; i < 8; i++) {
                const int slot = tid + i * 128;     // 0..1023
                const int nn = slot & 63, kp = slot >> 6;
                const int kk = k0 + 2 * kp;
                const int jj = j0 + nn;
                float v0 = 0.f, v1 = 0.f;
                if (kk < K && jj < N) {
                    v0 = __ldg(W + (long)kk * N + jj);
                    v1 = __ldg(W + (long)(kk + 1) * N + jj);   // K even
                }
                unsigned h, l;
                split2(v0, v1, h, l);
                Wh[nn][kp] = h;
                Wl[nn][kp] = l;
            }
        }
        __syncthreads();
        // ---- 2 x k16 mma steps, 3-term ----
#pragma unroll
        for (int kb = 0; kb < 2; kb++) {
            unsigned ah[2][4], al[2][4], bh[2][2], bl[2][2];
#pragma unroll
            for (int mt = 0; mt < 2; mt++) {
                const int m0 = mt * 16;
                ah[mt][0] = Ah[m0 + gr][kb * 8 + gq];
                ah[mt][1] = Ah[m0 + gr + 8][kb * 8 + gq];
                ah[mt][2] = Ah[m0 + gr][kb * 8 + gq + 4];
                ah[mt][3] = Ah[m0 + gr + 8][kb * 8 + gq + 4];
                al[mt][0] = Al[m0 + gr][kb * 8 + gq];
                al[mt][1] = Al[m0 + gr + 8][kb * 8 + gq];
                al[mt][2] = Al[m0 + gr][kb * 8 + gq + 4];
                al[mt][3] = Al[m0 + gr + 8][kb * 8 + gq + 4];
            }
#pragma unroll
            for (int nt = 0; nt < 2; nt++) {
                const int nc = warp * 16 + nt * 8 + gr;
                bh[nt][0] = Wh[nc][kb * 8 + gq];
                bh[nt][1] = Wh[nc][kb * 8 + gq + 4];
                bl[nt][0] = Wl[nc][kb * 8 + gq];
                bl[nt][1] = Wl[nc][kb * 8 + gq + 4];
            }
#pragma unroll
            for (int mt = 0; mt < 2; mt++)
#pragma unroll
                for (int nt = 0; nt < 2; nt++) {
                    mma_bf16(acc[mt][nt], ah[mt], bh[nt]);
                    mma_bf16(acc[mt][nt], al[mt], bh[nt]);
                    mma_bf16(acc[mt][nt], ah[mt], bl[nt]);
                }
        }
    }

    // ---- epilogue ----
#pragma unroll
    for (int mt = 0; mt < 2; mt++) {
#pragma unroll
        for (int nt = 0; nt < 2; nt++) {
            const float* ac = acc[mt][nt];
            const int row0 = mt * 16 + gr;
            const int col  = j0 + warp * 16 + nt * 8 + 2 * gq;
            if (ATOMIC) {
                if (col < N) {
                    atomicAdd(&C[(long)row0 * ldc + col], ac[0]);
                    atomicAdd(&C[(long)(row0 + 8) * ldc + col], ac[2]);
                }
                if (col + 1 < N) {
                    atomicAdd(&C[(long)row0 * ldc + col + 1], ac[1]);
                    atomicAdd(&C[(long)(row0 + 8) * ldc + col + 1], ac[3]);
                }
            } else {
                const float* bn = bias + (long)n * strideBias_n;
#pragma unroll
                for (int h = 0; h < 2; h++) {
                    const int j = col + h;
                    if (j < N) {
                        float v0 = ac[h]     + bn[j];
                        float v1 = ac[h + 2] + bn[j];
                        if (ORELU) { v0 = fmaxf(v0, 0.f); v1 = fmaxf(v1, 0.f); }
                        C[(long)row0 * ldc + j] = v0;
                        C[(long)(row0 + 8) * ldc + j] = v1;
                    }
                }
            }
        }
    }
}

// ---------------- launch ----------------
extern "C" void kernel_launch(void* const* d_in, const int* in_sizes, int n_in,
                              void* d_out, int out_size)
{
    const float* x   = (const float*)d_in[0];
    const float* cw1 = (const float*)d_in[1];
    const float* cb1 = (const float*)d_in[2];
    const float* cw2 = (const float*)d_in[3];
    const float* cb2 = (const float*)d_in[4];
    const float* cw3 = (const float*)d_in[5];
    const float* cb3 = (const float*)d_in[6];
    const float* wa  = (const float*)d_in[7];
    const float* ba  = (const float*)d_in[8];
    const float* ew1 = (const float*)d_in[9];
    const float* eb1 = (const float*)d_in[10];
    const float* ew2 = (const float*)d_in[11];
    const float* eb2 = (const float*)d_in[12];
    const float* ew3 = (const float*)d_in[13];
    const float* eb3 = (const float*)d_in[14];
    const float* fw1 = (const float*)d_in[15];
    const float* fb1 = (const float*)d_in[16];
    const float* fw2 = (const float*)d_in[17];
    const float* fb2 = (const float*)d_in[18];
    const float* fw3 = (const float*)d_in[19];
    const float* fb3 = (const float*)d_in[20];
    float* out = (float*)d_out;

    float *a1, *a2, *f, *lg, *att, *h1, *h2, *e, *g1, *g2;
    unsigned *wh2, *wl2, *wh3, *wl3;
    cudaGetSymbolAddress((void**)&a1,  g_a1);
    cudaGetSymbolAddress((void**)&a2,  g_a2);
    cudaGetSymbolAddress((void**)&f,   g_f);
    cudaGetSymbolAddress((void**)&lg,  g_lg);
    cudaGetSymbolAddress((void**)&att, g_at);
    cudaGetSymbolAddress((void**)&h1,  g_h1);
    cudaGetSymbolAddress((void**)&h2,  g_h2);
    cudaGetSymbolAddress((void**)&e,   g_e);
    cudaGetSymbolAddress((void**)&g1,  g_g1);
    cudaGetSymbolAddress((void**)&g2,  g_g2);
    cudaGetSymbolAddress((void**)&wh2, g_wh2);
    cudaGetSymbolAddress((void**)&wl2, g_wl2);
    cudaGetSymbolAddress((void**)&wh3, g_wh3);
    cudaGetSymbolAddress((void**)&wl3, g_wl3);

    // conv weight prep (bf16 hi/lo pair planes)
    conv_wprep_kernel<<<36, 256>>>(cw2, wh2, wl2, 32, 64);
    conv_wprep_kernel<<<144, 256>>>(cw3, wh3, wl3, 64, 128);

    // CNN stem
    conv_pool_kernel<3, 8><<<dim3(49, 4, 32), 256>>>(x, cw1, cb1, a1, 224, 224, 32);
    conv_bf_kernel<<<dim3(7, 14, 32), 256>>>(a1, wh2, wl2, cb2, a2, 112, 112, 32, 64, 1);
    conv_bf_kernel<<<dim3(4, 7, 64), 256>>>(a2, wh3, wl3, cb3, f, 56, 56, 64, 128, 2);

    // attention over feature maps
    attn_logits_kernel<<<dim3(128, 32), 128>>>(f, wa, ba, lg);
    attn_softmax_kernel<<<32, 128>>>(lg, att);

    // experts (bf16 3-term; att-scale fused into E1 A-load; bias+relu on store)
    gemm_bf_kernel<false, true, false, true><<<dim3(13, 128, 1), 128>>>(
        f, 784L, 128L * 784, att, ew1, 784L * 784, eb1, 784L, h1, 784L, 128L * 784, 784, 784);
    gemm_bf_kernel<false, false, false, true><<<dim3(7, 128, 1), 128>>>(
        h1, 784L, 128L * 784, nullptr, ew2, 784L * 392, eb2, 392L, h2, 392L, 128L * 392, 784, 392);
    gemm_bf_kernel<false, false, false, true><<<dim3(1, 128, 1), 128>>>(
        h2, 392L, 128L * 392, nullptr, ew3, 392L * 64, eb3, 64L, e, 64L, 8192L, 392, 64);

    // head
    gemm_bf_kernel<false, false, false, true><<<dim3(128, 1, 1), 128>>>(
        e, 0L, 8192L, nullptr, fw1, 0L, fb1, 0L, g1, 0L, 8192L, 8192, 8192);

    init_bias_kernel<<<512, 256>>>(g2, fb2, FHID_, B_);
    gemm_bf_kernel<false, false, true, false><<<dim3(64, 1, 2), 128>>>(
        g1, 0L, 8192L, nullptr, fw2, 0L, nullptr, 0L, g2, 0L, 4096L, 8192, 4096);

    init_bias_kernel<<<7, 256>>>(out, fb3, OUT_, B_);
    gemm_bf_kernel<true, false, true, false><<<dim3(1, 1, 16), 128>>>(
        g2, 0L, 4096L, nullptr, fw3, 0L, nullptr, 0L, out, 0L, 53L, 4096, 53);
}

// round 12
// speedup vs baseline: 4.3959x; 2.0005x over previous
#include <cuda_runtime.h>
#include <math.h>

#define B_   32
#define NF_  128
#define FLAT_ 784
#define HID2_ 392
#define EO_  64
#define FIN_ 8192
#define FHID_ 4096
#define OUT_ 53

// ---------------- scratch (static device allocations) ----------------
__device__ float g_a1[32 * 32 * 112 * 112];   // conv1 out (pooled)
__device__ float g_a2[32 * 64 * 56 * 56];     // conv2 out
__device__ float g_f [32 * 128 * 28 * 28];    // conv3 out == f [B][NF][784]
__device__ float g_lg[32 * 128];
__device__ float g_at[32 * 128];
__device__ float g_h1[32 * 128 * 784];
__device__ float g_h2[32 * 128 * 392];
__device__ float g_e [32 * 8192];
__device__ float g_g1[32 * 8192];
__device__ float g_g2[32 * 4096];
// conv weights as bf16 pairs over ci: [tap][cip][co], hi & lo planes
__device__ unsigned g_wh2[9 * 16 * 64];
__device__ unsigned g_wl2[9 * 16 * 64];
__device__ unsigned g_wh3[9 * 32 * 128];
__device__ unsigned g_wl3[9 * 32 * 128];

// ---------------- bf16 split helpers ----------------
__device__ __forceinline__ void split2(float x, float y, unsigned& h, unsigned& l) {
    asm("cvt.rn.bf16x2.f32 %0, %1, %2;" : "=r"(h) : "f"(y), "f"(x));
    float rx = x - __uint_as_float(h << 16);
    float ry = y - __uint_as_float(h & 0xffff0000u);
    asm("cvt.rn.bf16x2.f32 %0, %1, %2;" : "=r"(l) : "f"(ry), "f"(rx));
}
__device__ __forceinline__ void mma_bf16(float* c, const unsigned* a, const unsigned* b) {
    asm("mma.sync.aligned.m16n8k16.row.col.f32.bf16.bf16.f32 "
        "{%0,%1,%2,%3}, {%4,%5,%6,%7}, {%8,%9}, {%0,%1,%2,%3};"
        : "+f"(c[0]), "+f"(c[1]), "+f"(c[2]), "+f"(c[3])
        : "r"(a[0]), "r"(a[1]), "r"(a[2]), "r"(a[3]), "r"(b[0]), "r"(b[1]));
}

// ---------------- cp.async helpers ----------------
__device__ __forceinline__ void cpa16(unsigned dst, const void* src, bool pred) {
    int b = pred ? 16 : 0;
    asm volatile("cp.async.cg.shared.global [%0], [%1], 16, %2;" :: "r"(dst), "l"(src), "r"(b));
}
__device__ __forceinline__ void cpa4(unsigned dst, const void* src, bool pred) {
    int b = pred ? 4 : 0;
    asm volatile("cp.async.ca.shared.global [%0], [%1], 4, %2;" :: "r"(dst), "l"(src), "r"(b));
}
__device__ __forceinline__ void cpa_commit() {
    asm volatile("cp.async.commit_group;" ::: "memory");
}
__device__ __forceinline__ void cpa_wait1() {
    asm volatile("cp.async.wait_group 1;" ::: "memory");
}

// ---------------- conv1: fused conv3x3(SAME)+bias+relu+maxpool2 (fp32, CI=3) ----------------
template<int CI, int CO_T>
__global__ __launch_bounds__(256)
void conv_pool_kernel(const float* __restrict__ in, const float* __restrict__ w,
                      const float* __restrict__ bias, float* __restrict__ out,
                      int H, int W, int CO)
{
    __shared__ float sw[CO_T * CI * 9];
    const int tid = threadIdx.x;
    const int co0 = blockIdx.y * CO_T;
    const int b   = blockIdx.z;

    for (int i = tid; i < CO_T * CI * 9; i += blockDim.x)
        sw[i] = w[(long)co0 * CI * 9 + i];
    __syncthreads();

    const int HP = H >> 1, WP = W >> 1;
    const int p = blockIdx.x * blockDim.x + tid;
    if (p >= HP * WP) return;
    const int py = p / WP, px = p % WP;
    const int y0 = 2 * py, x0 = 2 * px;

    float acc[CO_T][4];
#pragma unroll
    for (int t = 0; t < CO_T; t++)
        acc[t][0] = acc[t][1] = acc[t][2] = acc[t][3] = 0.f;

    for (int ci = 0; ci < CI; ci++) {
        const float* ip = in + ((long)(b * CI + ci)) * H * W;
        float v[4][4];
#pragma unroll
        for (int r = 0; r < 4; r++) {
            const int yy = y0 - 1 + r;
            const bool yok = (yy >= 0) && (yy < H);
#pragma unroll
            for (int c = 0; c < 4; c++) {
                const int xx = x0 - 1 + c;
                const bool ok = yok && (xx >= 0) && (xx < W);
                v[r][c] = ok ? __ldg(ip + (long)yy * W + xx) : 0.f;
            }
        }
        const float* swc = sw + ci * 9;
#pragma unroll
        for (int t = 0; t < CO_T; t++) {
            const float* wt = swc + t * CI * 9;
#pragma unroll
            for (int ky = 0; ky < 3; ky++)
#pragma unroll
                for (int kx = 0; kx < 3; kx++) {
                    const float wv = wt[ky * 3 + kx];
                    acc[t][0] = fmaf(v[ky    ][kx    ], wv, acc[t][0]);
                    acc[t][1] = fmaf(v[ky    ][kx + 1], wv, acc[t][1]);
                    acc[t][2] = fmaf(v[ky + 1][kx    ], wv, acc[t][2]);
                    acc[t][3] = fmaf(v[ky + 1][kx + 1], wv, acc[t][3]);
                }
        }
    }
#pragma unroll
    for (int t = 0; t < CO_T; t++) {
        const float bv = bias[co0 + t];
        float m = fmaxf(fmaxf(acc[t][0], acc[t][1]), fmaxf(acc[t][2], acc[t][3])) + bv;
        m = fmaxf(m, 0.f);
        out[(((long)b * CO + co0 + t) * HP + py) * WP + px] = m;
    }
}

// ---------------- conv weight prep ----------------
__global__ void conv_wprep_kernel(const float* __restrict__ w,
                                  unsigned* __restrict__ whi, unsigned* __restrict__ wlo,
                                  int CI, int CO)
{
    const int idx = blockIdx.x * blockDim.x + threadIdx.x;
    const int CIP = CI >> 1;
    const int total = 9 * CIP * CO;
    if (idx >= total) return;
    const int co  = idx % CO;
    const int rest = idx / CO;
    const int cip = rest % CIP;
    const int tap = rest / CIP;
    const float v0 = w[((long)co * CI + 2 * cip)     * 9 + tap];
    const float v1 = w[((long)co * CI + 2 * cip + 1) * 9 + tap];
    unsigned h, l;
    split2(v0, v1, h, l);
    whi[idx] = h;
    wlo[idx] = l;
}

// ---------------- conv2/3: implicit-GEMM bf16 3-term, conv+bias+relu+pool ----------------
__global__ __launch_bounds__(256)
void conv_bf_kernel(const float* __restrict__ in,
                    const unsigned* __restrict__ whi, const unsigned* __restrict__ wlo,
                    const float* __restrict__ bias, float* __restrict__ out,
                    int H, int W, int CItot, int COtot, int coBlocks)
{
    const int tid   = threadIdx.x;
    const int warp  = tid >> 5;
    const int lane  = tid & 31;
    const int warpM = warp >> 1;
    const int warpN = warp & 1;
    const int gr    = lane >> 2;
    const int gq    = lane & 3;
    const int b     = blockIdx.z / coBlocks;
    const int co0   = (blockIdx.z % coBlocks) * 64;
    const int x0    = blockIdx.x * 16;
    const int y0    = blockIdx.y * 8;
    const int HP = H >> 1, WP = W >> 1;
    const int CIP = CItot >> 1;

    __shared__ __align__(16) unsigned char raw[34816];
    unsigned* pH  = (unsigned*)raw;                  // [cip16][10][20] stride 200
    unsigned* pL  = (unsigned*)(raw + 12800);
    unsigned* wHs = (unsigned*)(raw + 25600);        // [cip16][72]
    unsigned* wLs = (unsigned*)(raw + 30208);
    float*    preS = (float*)raw;                    // [128][65] epilogue alias

    float acc[2][4][4];
#pragma unroll
    for (int mt = 0; mt < 2; mt++)
#pragma unroll
        for (int nt = 0; nt < 4; nt++)
#pragma unroll
            for (int i = 0; i < 4; i++) acc[mt][nt][i] = 0.f;

    const long HW = (long)H * W;

    for (int ci0 = 0; ci0 < CItot; ci0 += 32) {
        __syncthreads();
        for (int idx = tid; idx < 2880; idx += 256) {
            const int cip = idx / 180, rem = idx % 180;
            const int r = rem / 18, c = rem % 18;
            const int y = y0 - 1 + r, x = x0 - 1 + c;
            float v0 = 0.f, v1 = 0.f;
            if (y >= 0 && y < H && x >= 0 && x < W) {
                const float* ip = in + ((long)(b * CItot + ci0 + 2 * cip) * H + y) * W + x;
                v0 = __ldg(ip);
                v1 = __ldg(ip + HW);
            }
            unsigned h, l;
            split2(v0, v1, h, l);
            pH[cip * 200 + r * 20 + c] = h;
            pL[cip * 200 + r * 20 + c] = l;
        }
        const int cip0 = ci0 >> 1;
        for (int tap = 0; tap < 9; tap++) {
            __syncthreads();
#pragma unroll
            for (int i = 0; i < 4; i++) {
                const int slot = tid + i * 256;
                const int cip = slot >> 6, co = slot & 63;
                const long src = ((long)tap * CIP + cip0 + cip) * COtot + co0 + co;
                wHs[cip * 72 + co] = __ldg(whi + src);
                wLs[cip * 72 + co] = __ldg(wlo + src);
            }
            __syncthreads();
            const int ky = tap / 3, kx = tap % 3;
#pragma unroll
            for (int kb = 0; kb < 2; kb++) {
                unsigned ah[2][4], al[2][4];
#pragma unroll
                for (int mt = 0; mt < 2; mt++) {
                    const int yrow = 2 * warpM + mt + ky;
                    const unsigned* bh_ = pH + (kb * 8 + gq) * 200 + yrow * 20 + kx;
                    const unsigned* bl_ = pL + (kb * 8 + gq) * 200 + yrow * 20 + kx;
                    ah[mt][0] = bh_[gr];       ah[mt][1] = bh_[gr + 8];
                    ah[mt][2] = bh_[800 + gr]; ah[mt][3] = bh_[800 + gr + 8];
                    al[mt][0] = bl_[gr];       al[mt][1] = bl_[gr + 8];
                    al[mt][2] = bl_[800 + gr]; al[mt][3] = bl_[800 + gr + 8];
                }
                unsigned bh[4][2], bl[4][2];
#pragma unroll
                for (int nt = 0; nt < 4; nt++) {
                    const int col = warpN * 32 + nt * 8 + gr;
                    bh[nt][0] = wHs[(kb * 8 + gq) * 72 + col];
                    bh[nt][1] = wHs[(kb * 8 + gq + 4) * 72 + col];
                    bl[nt][0] = wLs[(kb * 8 + gq) * 72 + col];
                    bl[nt][1] = wLs[(kb * 8 + gq + 4) * 72 + col];
                }
#pragma unroll
                for (int mt = 0; mt < 2; mt++)
#pragma unroll
                    for (int nt = 0; nt < 4; nt++) {
                        mma_bf16(acc[mt][nt], ah[mt], bh[nt]);
                        mma_bf16(acc[mt][nt], al[mt], bh[nt]);
                        mma_bf16(acc[mt][nt], ah[mt], bl[nt]);
                    }
            }
        }
    }

    __syncthreads();
#pragma unroll
    for (int mt = 0; mt < 2; mt++)
#pragma unroll
        for (int nt = 0; nt < 4; nt++) {
            const int m0 = (2 * warpM + mt) * 16;
            const int cc = warpN * 32 + nt * 8 + 2 * gq;
            const float* ac = acc[mt][nt];
            preS[(m0 + gr) * 65 + cc]         = ac[0];
            preS[(m0 + gr) * 65 + cc + 1]     = ac[1];
            preS[(m0 + gr + 8) * 65 + cc]     = ac[2];
            preS[(m0 + gr + 8) * 65 + cc + 1] = ac[3];
        }
    __syncthreads();
    for (int idx = tid; idx < 2048; idx += 256) {
        const int pp = idx & 31;
        const int co = idx >> 5;
        const int lx = (pp & 7) * 2, ly = (pp >> 3) * 2;
        const int m = ly * 16 + lx;
        float v = fmaxf(fmaxf(preS[m * 65 + co], preS[(m + 1) * 65 + co]),
                        fmaxf(preS[(m + 16) * 65 + co], preS[(m + 17) * 65 + co]));
        v = fmaxf(v + bias[co0 + co], 0.f);
        const int pxg = (x0 >> 1) + (pp & 7);
        const int pyg = (y0 >> 1) + (pp >> 3);
        if (pxg < WP && pyg < HP)
            out[((long)(b * COtot + co0 + co) * HP + pyg) * WP + pxg] = v;
    }
}

// ---------------- attention ----------------
__global__ void attn_logits_kernel(const float* __restrict__ f, const float* __restrict__ wa,
                                   const float* __restrict__ ba, float* __restrict__ logits)
{
    const int n = blockIdx.x, b = blockIdx.y;
    const float* fp = f + ((long)b * NF_ + n) * FLAT_;
    float s = 0.f;
    for (int k = threadIdx.x; k < FLAT_; k += 128)
        s += fp[k] * wa[k];
    __shared__ float red[128];
    red[threadIdx.x] = s;
    __syncthreads();
    for (int off = 64; off > 0; off >>= 1) {
        if (threadIdx.x < off) red[threadIdx.x] += red[threadIdx.x + off];
        __syncthreads();
    }
    if (threadIdx.x == 0) logits[b * NF_ + n] = red[0] + ba[0];
}

__global__ void attn_softmax_kernel(const float* __restrict__ logits, float* __restrict__ att)
{
    __shared__ float sh[128];
    const int b = blockIdx.x, n = threadIdx.x;
    const float v = logits[b * NF_ + n];
    sh[n] = v;
    __syncthreads();
    for (int off = 64; off > 0; off >>= 1) {
        if (n < off) sh[n] = fmaxf(sh[n], sh[n + off]);
        __syncthreads();
    }
    const float mx = sh[0];
    __syncthreads();
    const float e = expf(v - mx);
    sh[n] = e;
    __syncthreads();
    for (int off = 64; off > 0; off >>= 1) {
        if (n < off) sh[n] += sh[n + off];
        __syncthreads();
    }
    att[b * NF_ + n] = e / sh[0];
}

// ---------------- init output with bias ----------------
__global__ void init_bias_kernel(float* __restrict__ C, const float* __restrict__ bias, int N, int M)
{
    const int i = blockIdx.x * blockDim.x + threadIdx.x;
    if (i < M * N) C[i] = bias[i % N];
}

// ---------------- bf16 3-term skinny GEMM, cp.async 3-stage pipeline ----------------
// C[32,N] = op(A[32,K]) @ W[K,N]. 128 threads = 4 warps over N (16 cols each).
// Tile M32 x N64 x K32. Raw fp32 staged via cp.async; hi/lo split at fragment read.
#define GSTAGES 3
template<bool ARELU, bool ASCALE, bool ATOMIC, bool ORELU>
__global__ __launch_bounds__(128)
void gemm_bf_kernel(const float* __restrict__ A, long strideA_n, long lda,
                    const float* __restrict__ scale,
                    const float* __restrict__ W, long strideW_n,
                    const float* __restrict__ bias, long strideBias_n,
                    float* __restrict__ C, long strideC_n, long ldc,
                    int K, int N)
{
    const int n    = blockIdx.y;
    const int j0   = blockIdx.x * 64;
    const int tid  = threadIdx.x;
    const int warp = tid >> 5;
    const int lane = tid & 31;
    const int gr   = lane >> 2;
    const int gq   = lane & 3;

    A += (long)n * strideA_n;
    W += (long)n * strideW_n;
    C += (long)n * strideC_n;

    const int kchunks = (K + 31) >> 5;
    const int per = (kchunks + gridDim.z - 1) / gridDim.z;
    const int c0 = blockIdx.z * per;
    const int c1 = min(kchunks, c0 + per);

    __shared__ __align__(16) float Wst[GSTAGES][32][68];
    __shared__ __align__(16) float Ast[GSTAGES][32][36];
    __shared__ float ssc[32];

    if (ASCALE && tid < 32) ssc[tid] = scale[(long)tid * NF_ + n];

    const bool vecN = ((N & 3) == 0);

    // ---- stage issue: raw fp32 cp.async (zero-fill OOB) ----
    auto issue = [&](int stage, int cc) {
        const int k0 = cc << 5;
        // A: 32 rows x 8 float4 (K%4==0 for all layers)
#pragma unroll
        for (int i = 0; i < 2; i++) {
            const int slot = tid + i * 128;
            const int m = slot >> 3, q = slot & 7;
            const int kk = k0 + q * 4;
            unsigned dst = (unsigned)__cvta_generic_to_shared(&Ast[stage][m][q * 4]);
            cpa16(dst, A + (long)m * lda + kk, kk < K);
        }
        if (vecN) {
#pragma unroll
            for (int i = 0; i < 4; i++) {
                const int slot = tid + i * 128;
                const int kr = slot >> 4, c4 = (slot & 15) * 4;
                const int kk = k0 + kr, jj = j0 + c4;
                unsigned dst = (unsigned)__cvta_generic_to_shared(&Wst[stage][kr][c4]);
                cpa16(dst, W + (long)kk * N + jj, (kk < K) && (jj < N));
            }
        } else {
#pragma unroll
            for (int i = 0; i < 16; i++) {
                const int slot = tid + i * 128;
                const int kr = slot >> 6, nn = slot & 63;
                const int kk = k0 + kr, jj = j0 + nn;
                const bool ok = (kk < K) && (jj < N);
                unsigned dst = (unsigned)__cvta_generic_to_shared(&Wst[stage][kr][nn]);
                cpa4(dst, ok ? (W + (long)kk * N + jj) : W, ok);
            }
        }
        cpa_commit();
    };

    float acc[2][2][4];
#pragma unroll
    for (int mt = 0; mt < 2; mt++)
#pragma unroll
        for (int nt = 0; nt < 2; nt++)
#pragma unroll
            for (int i = 0; i < 4; i++) acc[mt][nt][i] = 0.f;

    // prologue: fill 2 stages
    for (int p = 0; p < GSTAGES - 1; p++) {
        if (c0 + p < c1) issue(p, c0 + p);
        else cpa_commit();
    }

    for (int cc = c0; cc < c1; cc++) {
        cpa_wait1();
        __syncthreads();
        // issue chunk cc+2 into the stage consumed last iteration (safe after sync)
        const int t = cc - c0;
        if (cc + GSTAGES - 1 < c1) issue((t + GSTAGES - 1) % GSTAGES, cc + GSTAGES - 1);
        else cpa_commit();

        const int s = t % GSTAGES;
        const float* Ab = &Ast[s][0][0];
        const float* Wb = &Wst[s][0][0];
#pragma unroll
        for (int kb = 0; kb < 2; kb++) {
            const int k16 = kb * 16;
            unsigned ah[2][4], al[2][4], bh[2][2], bl[2][2];
#pragma unroll
            for (int mt = 0; mt < 2; mt++) {
                const int m0 = mt * 16;
                float2 v0 = *(const float2*)(Ab + (m0 + gr) * 36 + k16 + 2 * gq);
                float2 v1 = *(const float2*)(Ab + (m0 + gr + 8) * 36 + k16 + 2 * gq);
                float2 v2 = *(const float2*)(Ab + (m0 + gr) * 36 + k16 + 8 + 2 * gq);
                float2 v3 = *(const float2*)(Ab + (m0 + gr + 8) * 36 + k16 + 8 + 2 * gq);
                if (ARELU) {
                    v0.x = fmaxf(v0.x, 0.f); v0.y = fmaxf(v0.y, 0.f);
                    v1.x = fmaxf(v1.x, 0.f); v1.y = fmaxf(v1.y, 0.f);
                    v2.x = fmaxf(v2.x, 0.f); v2.y = fmaxf(v2.y, 0.f);
                    v3.x = fmaxf(v3.x, 0.f); v3.y = fmaxf(v3.y, 0.f);
                }
                if (ASCALE) {
                    const float s0 = ssc[m0 + gr], s1 = ssc[m0 + gr + 8];
                    v0.x *= s0; v0.y *= s0; v2.x *= s0; v2.y *= s0;
                    v1.x *= s1; v1.y *= s1; v3.x *= s1; v3.y *= s1;
                }
                split2(v0.x, v0.y, ah[mt][0], al[mt][0]);
                split2(v1.x, v1.y, ah[mt][1], al[mt][1]);
                split2(v2.x, v2.y, ah[mt][2], al[mt][2]);
                split2(v3.x, v3.y, ah[mt][3], al[mt][3]);
            }
#pragma unroll
            for (int nt = 0; nt < 2; nt++) {
                const int nc = warp * 16 + nt * 8 + gr;
                float w0 = Wb[(k16 + 2 * gq) * 68 + nc];
                float w1 = Wb[(k16 + 2 * gq + 1) * 68 + nc];
                split2(w0, w1, bh[nt][0], bl[nt][0]);
                w0 = Wb[(k16 + 8 + 2 * gq) * 68 + nc];
                w1 = Wb[(k16 + 9 + 2 * gq) * 68 + nc];
                split2(w0, w1, bh[nt][1], bl[nt][1]);
            }
#pragma unroll
            for (int mt = 0; mt < 2; mt++)
#pragma unroll
                for (int nt = 0; nt < 2; nt++) {
                    mma_bf16(acc[mt][nt], ah[mt], bh[nt]);
                    mma_bf16(acc[mt][nt], al[mt], bh[nt]);
                    mma_bf16(acc[mt][nt], ah[mt], bl[nt]);
                }
        }
        __syncthreads();   // all warps done with stage s before it is refilled next iters
    }

    // ---- epilogue ----
#pragma unroll
    for (int mt = 0; mt < 2; mt++) {
#pragma unroll
        for (int nt = 0; nt < 2; nt++) {
            const float* ac = acc[mt][nt];
            const int row0 = mt * 16 + gr;
            const int col  = j0 + warp * 16 + nt * 8 + 2 * gq;
            if (ATOMIC) {
                if (col < N) {
                    atomicAdd(&C[(long)row0 * ldc + col], ac[0]);
                    atomicAdd(&C[(long)(row0 + 8) * ldc + col], ac[2]);
                }
                if (col + 1 < N) {
                    atomicAdd(&C[(long)row0 * ldc + col + 1], ac[1]);
                    atomicAdd(&C[(long)(row0 + 8) * ldc + col + 1], ac[3]);
                }
            } else {
                const float* bn = bias + (long)n * strideBias_n;
#pragma unroll
                for (int h = 0; h < 2; h++) {
                    const int j = col + h;
                    if (j < N) {
                        float v0 = ac[h]     + bn[j];
                        float v1 = ac[h + 2] + bn[j];
                        if (ORELU) { v0 = fmaxf(v0, 0.f); v1 = fmaxf(v1, 0.f); }
                        C[(long)row0 * ldc + j] = v0;
                        C[(long)(row0 + 8) * ldc + j] = v1;
                    }
                }
            }
        }
    }
}

// ---------------- launch ----------------
extern "C" void kernel_launch(void* const* d_in, const int* in_sizes, int n_in,
                              void* d_out, int out_size)
{
    const float* x   = (const float*)d_in[0];
    const float* cw1 = (const float*)d_in[1];
    const float* cb1 = (const float*)d_in[2];
    const float* cw2 = (const float*)d_in[3];
    const float* cb2 = (const float*)d_in[4];
    const float* cw3 = (const float*)d_in[5];
    const float* cb3 = (const float*)d_in[6];
    const float* wa  = (const float*)d_in[7];
    const float* ba  = (const float*)d_in[8];
    const float* ew1 = (const float*)d_in[9];
    const float* eb1 = (const float*)d_in[10];
    const float* ew2 = (const float*)d_in[11];
    const float* eb2 = (const float*)d_in[12];
    const float* ew3 = (const float*)d_in[13];
    const float* eb3 = (const float*)d_in[14];
    const float* fw1 = (const float*)d_in[15];
    const float* fb1 = (const float*)d_in[16];
    const float* fw2 = (const float*)d_in[17];
    const float* fb2 = (const float*)d_in[18];
    const float* fw3 = (const float*)d_in[19];
    const float* fb3 = (const float*)d_in[20];
    float* out = (float*)d_out;

    float *a1, *a2, *f, *lg, *att, *h1, *h2, *e, *g1, *g2;
    unsigned *wh2, *wl2, *wh3, *wl3;
    cudaGetSymbolAddress((void**)&a1,  g_a1);
    cudaGetSymbolAddress((void**)&a2,  g_a2);
    cudaGetSymbolAddress((void**)&f,   g_f);
    cudaGetSymbolAddress((void**)&lg,  g_lg);
    cudaGetSymbolAddress((void**)&att, g_at);
    cudaGetSymbolAddress((void**)&h1,  g_h1);
    cudaGetSymbolAddress((void**)&h2,  g_h2);
    cudaGetSymbolAddress((void**)&e,   g_e);
    cudaGetSymbolAddress((void**)&g1,  g_g1);
    cudaGetSymbolAddress((void**)&g2,  g_g2);
    cudaGetSymbolAddress((void**)&wh2, g_wh2);
    cudaGetSymbolAddress((void**)&wl2, g_wl2);
    cudaGetSymbolAddress((void**)&wh3, g_wh3);
    cudaGetSymbolAddress((void**)&wl3, g_wl3);

    conv_wprep_kernel<<<36, 256>>>(cw2, wh2, wl2, 32, 64);
    conv_wprep_kernel<<<144, 256>>>(cw3, wh3, wl3, 64, 128);

    // CNN stem
    conv_pool_kernel<3, 8><<<dim3(49, 4, 32), 256>>>(x, cw1, cb1, a1, 224, 224, 32);
    conv_bf_kernel<<<dim3(7, 14, 32), 256>>>(a1, wh2, wl2, cb2, a2, 112, 112, 32, 64, 1);
    conv_bf_kernel<<<dim3(4, 7, 64), 256>>>(a2, wh3, wl3, cb3, f, 56, 56, 64, 128, 2);

    // attention
    attn_logits_kernel<<<dim3(128, 32), 128>>>(f, wa, ba, lg);
    attn_softmax_kernel<<<32, 128>>>(lg, att);

    // experts
    gemm_bf_kernel<false, true, false, true><<<dim3(13, 128, 1), 128>>>(
        f, 784L, 128L * 784, att, ew1, 784L * 784, eb1, 784L, h1, 784L, 128L * 784, 784, 784);
    gemm_bf_kernel<false, false, false, true><<<dim3(7, 128, 1), 128>>>(
        h1, 784L, 128L * 784, nullptr, ew2, 784L * 392, eb2, 392L, h2, 392L, 128L * 392, 784, 392);
    gemm_bf_kernel<false, false, false, true><<<dim3(1, 128, 1), 128>>>(
        h2, 392L, 128L * 392, nullptr, ew3, 392L * 64, eb3, 64L, e, 64L, 8192L, 392, 64);

    // head
    gemm_bf_kernel<false, false, false, true><<<dim3(128, 1, 1), 128>>>(
        e, 0L, 8192L, nullptr, fw1, 0L, fb1, 0L, g1, 0L, 8192L, 8192, 8192);

    init_bias_kernel<<<512, 256>>>(g2, fb2, FHID_, B_);
    gemm_bf_kernel<false, false, true, false><<<dim3(64, 1, 2), 128>>>(
        g1, 0L, 8192L, nullptr, fw2, 0L, nullptr, 0L, g2, 0L, 4096L, 8192, 4096);

    init_bias_kernel<<<7, 256>>>(out, fb3, OUT_, B_);
    gemm_bf_kernel<true, false, true, false><<<dim3(1, 1, 16), 128>>>(
        g2, 0L, 4096L, nullptr, fw3, 0L, nullptr, 0L, out, 0L, 53L, 4096, 53);
}

// round 13
// speedup vs baseline: 4.9974x; 1.1368x over previous
#include <cuda_runtime.h>
#include <math.h>

#define B_   32
#define NF_  128
#define FLAT_ 784
#define HID2_ 392
#define EO_  64
#define FIN_ 8192
#define FHID_ 4096
#define OUT_ 53

// ---------------- scratch (static device allocations) ----------------
__device__ unsigned g_p1h[32 * 16 * 112 * 112];
__device__ unsigned g_p1l[32 * 16 * 112 * 112];
__device__ unsigned g_p2h[32 * 32 * 56 * 56];
__device__ unsigned g_p2l[32 * 32 * 56 * 56];
__device__ float g_f [32 * 128 * 28 * 28];
__device__ float g_lg[32 * 128];
__device__ float g_at[32 * 128];
__device__ float g_h1[32 * 128 * 784];
__device__ float g_h2[32 * 128 * 392];
__device__ float g_e [32 * 8192];
__device__ float g_g1[32 * 8192];
__device__ float g_g2[32 * 4096];
__device__ unsigned g_wh2[9 * 16 * 64];
__device__ unsigned g_wl2[9 * 16 * 64];
__device__ unsigned g_wh3[9 * 32 * 128];
__device__ unsigned g_wl3[9 * 32 * 128];

// ---------------- bf16 split helpers ----------------
__device__ __forceinline__ void split2(float x, float y, unsigned& h, unsigned& l) {
    asm("cvt.rn.bf16x2.f32 %0, %1, %2;" : "=r"(h) : "f"(y), "f"(x));
    float rx = x - __uint_as_float(h << 16);
    float ry = y - __uint_as_float(h & 0xffff0000u);
    asm("cvt.rn.bf16x2.f32 %0, %1, %2;" : "=r"(l) : "f"(ry), "f"(rx));
}
__device__ __forceinline__ void mma_bf16(float* c, const unsigned* a, const unsigned* b) {
    asm("mma.sync.aligned.m16n8k16.row.col.f32.bf16.bf16.f32 "
        "{%0,%1,%2,%3}, {%4,%5,%6,%7}, {%8,%9}, {%0,%1,%2,%3};"
        : "+f"(c[0]), "+f"(c[1]), "+f"(c[2]), "+f"(c[3])
        : "r"(a[0]), "r"(a[1]), "r"(a[2]), "r"(a[3]), "r"(b[0]), "r"(b[1]));
}

// ---------------- cp.async helpers ----------------
__device__ __forceinline__ void cpa16(unsigned dst, const void* src, bool pred) {
    int b = pred ? 16 : 0;
    asm volatile("cp.async.cg.shared.global [%0], [%1], 16, %2;" :: "r"(dst), "l"(src), "r"(b));
}
__device__ __forceinline__ void cpa4(unsigned dst, const void* src, bool pred) {
    int b = pred ? 4 : 0;
    asm volatile("cp.async.ca.shared.global [%0], [%1], 4, %2;" :: "r"(dst), "l"(src), "r"(b));
}
__device__ __forceinline__ void cpa_commit() {
    asm volatile("cp.async.commit_group;" ::: "memory");
}
__device__ __forceinline__ void cpa_wait0() {
    asm volatile("cp.async.wait_group 0;" ::: "memory");
}
__device__ __forceinline__ void cpa_wait1() {
    asm volatile("cp.async.wait_group 1;" ::: "memory");
}

// ---------------- conv1: fp32 conv3x3+bias+relu+pool -> bf16 pair planes ----------------
__global__ __launch_bounds__(256)
void conv1_kernel(const float* __restrict__ in, const float* __restrict__ w,
                  const float* __restrict__ bias,
                  unsigned* __restrict__ outH, unsigned* __restrict__ outL)
{
    const int CI = 3, CO_T = 8, H = 224, W = 224;
    __shared__ float sw[CO_T * CI * 9];
    const int tid = threadIdx.x;
    const int co0 = blockIdx.y * CO_T;
    const int b   = blockIdx.z;

    for (int i = tid; i < CO_T * CI * 9; i += 256)
        sw[i] = w[(long)co0 * CI * 9 + i];
    __syncthreads();

    const int HP = 112, WP = 112;
    const int p = blockIdx.x * 256 + tid;
    const int py = p / WP, px = p % WP;
    const int y0 = 2 * py, x0 = 2 * px;

    float acc[CO_T][4];
#pragma unroll
    for (int t = 0; t < CO_T; t++)
        acc[t][0] = acc[t][1] = acc[t][2] = acc[t][3] = 0.f;

    for (int ci = 0; ci < CI; ci++) {
        const float* ip = in + ((long)(b * CI + ci)) * H * W;
        float v[4][4];
#pragma unroll
        for (int r = 0; r < 4; r++) {
            const int yy = y0 - 1 + r;
            const bool yok = (yy >= 0) && (yy < H);
#pragma unroll
            for (int c = 0; c < 4; c++) {
                const int xx = x0 - 1 + c;
                const bool ok = yok && (xx >= 0) && (xx < W);
                v[r][c] = ok ? __ldg(ip + (long)yy * W + xx) : 0.f;
            }
        }
        const float* swc = sw + ci * 9;
#pragma unroll
        for (int t = 0; t < CO_T; t++) {
            const float* wt = swc + t * CI * 9;
#pragma unroll
            for (int ky = 0; ky < 3; ky++)
#pragma unroll
                for (int kx = 0; kx < 3; kx++) {
                    const float wv = wt[ky * 3 + kx];
                    acc[t][0] = fmaf(v[ky    ][kx    ], wv, acc[t][0]);
                    acc[t][1] = fmaf(v[ky    ][kx + 1], wv, acc[t][1]);
                    acc[t][2] = fmaf(v[ky + 1][kx    ], wv, acc[t][2]);
                    acc[t][3] = fmaf(v[ky + 1][kx + 1], wv, acc[t][3]);
                }
        }
    }
    const int cop0 = co0 >> 1;
#pragma unroll
    for (int t = 0; t < 4; t++) {
        float v0 = fmaxf(fmaxf(acc[2*t][0], acc[2*t][1]), fmaxf(acc[2*t][2], acc[2*t][3])) + bias[co0 + 2*t];
        float v1 = fmaxf(fmaxf(acc[2*t+1][0], acc[2*t+1][1]), fmaxf(acc[2*t+1][2], acc[2*t+1][3])) + bias[co0 + 2*t + 1];
        v0 = fmaxf(v0, 0.f); v1 = fmaxf(v1, 0.f);
        unsigned h, l;
        split2(v0, v1, h, l);
        const long off = ((long)(b * 16 + cop0 + t) * HP + py) * WP + px;
        outH[off] = h;
        outL[off] = l;
    }
}

// ---------------- conv weight prep ----------------
__global__ void conv_wprep_kernel(const float* __restrict__ w,
                                  unsigned* __restrict__ whi, unsigned* __restrict__ wlo,
                                  int CI, int CO)
{
    const int idx = blockIdx.x * blockDim.x + threadIdx.x;
    const int CIP = CI >> 1;
    const int total = 9 * CIP * CO;
    if (idx >= total) return;
    const int co  = idx % CO;
    const int rest = idx / CO;
    const int cip = rest % CIP;
    const int tap = rest / CIP;
    const float v0 = w[((long)co * CI + 2 * cip)     * 9 + tap];
    const float v1 = w[((long)co * CI + 2 * cip + 1) * 9 + tap];
    unsigned h, l;
    split2(v0, v1, h, l);
    whi[idx] = h;
    wlo[idx] = l;
}

// ---------------- zero kernel ----------------
__global__ void zero_kernel(float* __restrict__ p, int n)
{
    const int i = blockIdx.x * blockDim.x + threadIdx.x;
    if (i < n) p[i] = 0.f;
}

// ---------------- conv2/3: implicit-GEMM bf16 3-term from pair planes ----------------
template<bool PAIR_OUT, bool ATT>
__global__ __launch_bounds__(256)
void conv_bf_kernel(const unsigned* __restrict__ inH, const unsigned* __restrict__ inL,
                    const unsigned* __restrict__ whi, const unsigned* __restrict__ wlo,
                    const float* __restrict__ bias,
                    float* __restrict__ outF, unsigned* __restrict__ outH, unsigned* __restrict__ outL,
                    const float* __restrict__ wa, float* __restrict__ lg,
                    int H, int W, int CItot, int COtot, int coBlocks)
{
    const int tid   = threadIdx.x;
    const int warp  = tid >> 5;
    const int lane  = tid & 31;
    const int warpM = warp >> 1;
    const int warpN = warp & 1;
    const int gr    = lane >> 2;
    const int gq    = lane & 3;
    const int b     = blockIdx.z / coBlocks;
    const int co0   = (blockIdx.z % coBlocks) * 64;
    const int x0    = blockIdx.x * 16;
    const int y0    = blockIdx.y * 8;
    const int HP = H >> 1, WP = W >> 1;
    const int CIP = CItot >> 1;

    __shared__ __align__(16) unsigned char raw[44032];
    unsigned* pH  = (unsigned*)raw;                  // [16 cip][10][20] stride 200
    unsigned* pL  = (unsigned*)(raw + 12800);
    unsigned* wHs0 = (unsigned*)(raw + 25600);
    unsigned* wHs1 = (unsigned*)(raw + 30208);
    unsigned* wLs0 = (unsigned*)(raw + 34816);
    unsigned* wLs1 = (unsigned*)(raw + 39424);
    float*    preS = (float*)raw;                    // [128][65] epilogue alias

    float acc[2][4][4];
#pragma unroll
    for (int mt = 0; mt < 2; mt++)
#pragma unroll
        for (int nt = 0; nt < 4; nt++)
#pragma unroll
            for (int i = 0; i < 4; i++) acc[mt][nt][i] = 0.f;

    auto issue_w = [&](int stage, int tap, int cip0) {
        unsigned* wH = stage ? wHs1 : wHs0;
        unsigned* wL = stage ? wLs1 : wLs0;
        const int cip = tid >> 4, c4 = (tid & 15) * 4;
        const long src = ((long)tap * CIP + cip0 + cip) * COtot + co0 + c4;
        cpa16((unsigned)__cvta_generic_to_shared(wH + cip * 72 + c4), whi + src, true);
        cpa16((unsigned)__cvta_generic_to_shared(wL + cip * 72 + c4), wlo + src, true);
        cpa_commit();
    };

    for (int ci0 = 0; ci0 < CItot; ci0 += 32) {
        const int cip0 = ci0 >> 1;
        __syncthreads();
        issue_w(0, 0, cip0);
        for (int idx = tid; idx < 2880; idx += 256) {
            const int cip = idx / 180, rem = idx % 180;
            const int r = rem / 18, c = rem % 18;
            const int y = y0 - 1 + r, x = x0 - 1 + c;
            unsigned h = 0u, l = 0u;
            if (y >= 0 && y < H && x >= 0 && x < W) {
                const long off = ((long)(b * CIP + cip0 + cip) * H + y) * W + x;
                h = __ldg(inH + off);
                l = __ldg(inL + off);
            }
            pH[cip * 200 + r * 20 + c] = h;
            pL[cip * 200 + r * 20 + c] = l;
        }
        for (int tap = 0; tap < 9; tap++) {
            cpa_wait0();
            __syncthreads();
            if (tap < 8) issue_w((tap + 1) & 1, tap + 1, cip0);
            const unsigned* wH = (tap & 1) ? wHs1 : wHs0;
            const unsigned* wL = (tap & 1) ? wLs1 : wLs0;
            const int ky = tap / 3, kx = tap % 3;
#pragma unroll
            for (int kb = 0; kb < 2; kb++) {
                unsigned ah[2][4], al[2][4];
#pragma unroll
                for (int mt = 0; mt < 2; mt++) {
                    const int yrow = 2 * warpM + mt + ky;
                    const unsigned* bh_ = pH + (kb * 8 + gq) * 200 + yrow * 20 + kx;
                    const unsigned* bl_ = pL + (kb * 8 + gq) * 200 + yrow * 20 + kx;
                    ah[mt][0] = bh_[gr];       ah[mt][1] = bh_[gr + 8];
                    ah[mt][2] = bh_[800 + gr]; ah[mt][3] = bh_[800 + gr + 8];
                    al[mt][0] = bl_[gr];       al[mt][1] = bl_[gr + 8];
                    al[mt][2] = bl_[800 + gr]; al[mt][3] = bl_[800 + gr + 8];
                }
                unsigned bh[4][2], bl[4][2];
#pragma unroll
                for (int nt = 0; nt < 4; nt++) {
                    const int col = warpN * 32 + nt * 8 + gr;
                    bh[nt][0] = wH[(kb * 8 + gq) * 72 + col];
                    bh[nt][1] = wH[(kb * 8 + gq + 4) * 72 + col];
                    bl[nt][0] = wL[(kb * 8 + gq) * 72 + col];
                    bl[nt][1] = wL[(kb * 8 + gq + 4) * 72 + col];
                }
#pragma unroll
                for (int mt = 0; mt < 2; mt++)
#pragma unroll
                    for (int nt = 0; nt < 4; nt++) {
                        mma_bf16(acc[mt][nt], ah[mt], bh[nt]);
                        mma_bf16(acc[mt][nt], al[mt], bh[nt]);
                        mma_bf16(acc[mt][nt], ah[mt], bl[nt]);
                    }
            }
        }
    }

    __syncthreads();
#pragma unroll
    for (int mt = 0; mt < 2; mt++)
#pragma unroll
        for (int nt = 0; nt < 4; nt++) {
            const int m0 = (2 * warpM + mt) * 16;
            const int cc = warpN * 32 + nt * 8 + 2 * gq;
            const float* ac = acc[mt][nt];
            preS[(m0 + gr) * 65 + cc]         = ac[0];
            preS[(m0 + gr) * 65 + cc + 1]     = ac[1];
            preS[(m0 + gr + 8) * 65 + cc]     = ac[2];
            preS[(m0 + gr + 8) * 65 + cc + 1] = ac[3];
        }
    __syncthreads();

    if (PAIR_OUT) {
        const int COP = COtot >> 1;
        for (int idx = tid; idx < 1024; idx += 256) {
            const int pp = idx & 31;
            const int cop = idx >> 5;
            const int lx = (pp & 7) * 2, ly = (pp >> 3) * 2;
            const int m = ly * 16 + lx;
            const int c0c = 2 * cop;
            float v0 = fmaxf(fmaxf(preS[m * 65 + c0c], preS[(m + 1) * 65 + c0c]),
                             fmaxf(preS[(m + 16) * 65 + c0c], preS[(m + 17) * 65 + c0c]));
            float v1 = fmaxf(fmaxf(preS[m * 65 + c0c + 1], preS[(m + 1) * 65 + c0c + 1]),
                             fmaxf(preS[(m + 16) * 65 + c0c + 1], preS[(m + 17) * 65 + c0c + 1]));
            v0 = fmaxf(v0 + bias[co0 + c0c], 0.f);
            v1 = fmaxf(v1 + bias[co0 + c0c + 1], 0.f);
            const int pxg = (x0 >> 1) + (pp & 7);
            const int pyg = (y0 >> 1) + (pp >> 3);
            if (pxg < WP && pyg < HP) {
                unsigned h, l;
                split2(v0, v1, h, l);
                const long off = ((long)(b * COP + (co0 >> 1) + cop) * HP + pyg) * WP + pxg;
                outH[off] = h;
                outL[off] = l;
            }
        }
    } else {
        for (int idx = tid; idx < 2048; idx += 256) {
            const int pp = idx & 31;
            const int co = idx >> 5;
            const int lx = (pp & 7) * 2, ly = (pp >> 3) * 2;
            const int m = ly * 16 + lx;
            float v = fmaxf(fmaxf(preS[m * 65 + co], preS[(m + 1) * 65 + co]),
                            fmaxf(preS[(m + 16) * 65 + co], preS[(m + 17) * 65 + co]));
            v = fmaxf(v + bias[co0 + co], 0.f);
            const int pxg = (x0 >> 1) + (pp & 7);
            const int pyg = (y0 >> 1) + (pp >> 3);
            if (pxg < WP && pyg < HP)
                outF[((long)(b * COtot + co0 + co) * HP + pyg) * WP + pxg] = v;
        }
        if (ATT && tid < 64) {
            const int co = tid;
            const float bv = bias[co0 + co];
            float sum = 0.f;
            for (int pp = 0; pp < 32; pp++) {
                const int pxg = (x0 >> 1) + (pp & 7);
                const int pyg = (y0 >> 1) + (pp >> 3);
                if (pxg < WP && pyg < HP) {
                    const int m = (pp >> 3) * 2 * 16 + (pp & 7) * 2;
                    float v = fmaxf(fmaxf(preS[m * 65 + co], preS[(m + 1) * 65 + co]),
                                    fmaxf(preS[(m + 16) * 65 + co], preS[(m + 17) * 65 + co]));
                    v = fmaxf(v + bv, 0.f);
                    sum += v * __ldg(wa + pyg * WP + pxg);
                }
            }
            atomicAdd(&lg[b * NF_ + co0 + co], sum);
        }
    }
}

// ---------------- softmax over features (ba omitted: constant shift cancels) ----------------
__global__ void attn_softmax_kernel(const float* __restrict__ logits, float* __restrict__ att)
{
    __shared__ float sh[128];
    const int b = blockIdx.x, n = threadIdx.x;
    const float v = logits[b * NF_ + n];
    sh[n] = v;
    __syncthreads();
    for (int off = 64; off > 0; off >>= 1) {
        if (n < off) sh[n] = fmaxf(sh[n], sh[n + off]);
        __syncthreads();
    }
    const float mx = sh[0];
    __syncthreads();
    const float e = expf(v - mx);
    sh[n] = e;
    __syncthreads();
    for (int off = 64; off > 0; off >>= 1) {
        if (n < off) sh[n] += sh[n + off];
        __syncthreads();
    }
    att[b * NF_ + n] = e / sh[0];
}

// ---------------- init output with bias ----------------
__global__ void init_bias_kernel(float* __restrict__ C, const float* __restrict__ bias, int N, int M)
{
    const int i = blockIdx.x * blockDim.x + threadIdx.x;
    if (i < M * N) C[i] = bias[i % N];
}

// ---------------- bf16 3-term skinny GEMM, cp.async 3-stage pipeline ----------------
#define GSTAGES 3
template<bool ARELU, bool ASCALE, bool ATOMIC, bool ORELU>
__global__ __launch_bounds__(128)
void gemm_bf_kernel(const float* __restrict__ A, long strideA_n, long lda,
                    const float* __restrict__ scale,
                    const float* __restrict__ W, long strideW_n,
                    const float* __restrict__ bias, long strideBias_n,
                    float* __restrict__ C, long strideC_n, long ldc,
                    int K, int N)
{
    const int n    = blockIdx.y;
    const int j0   = blockIdx.x * 64;
    const int tid  = threadIdx.x;
    const int warp = tid >> 5;
    const int lane = tid & 31;
    const int gr   = lane >> 2;
    const int gq   = lane & 3;

    A += (long)n * strideA_n;
    W += (long)n * strideW_n;
    C += (long)n * strideC_n;

    const int kchunks = (K + 31) >> 5;
    const int per = (kchunks + gridDim.z - 1) / gridDim.z;
    const int c0 = blockIdx.z * per;
    const int c1 = min(kchunks, c0 + per);

    __shared__ __align__(16) float Wst[GSTAGES][32][68];
    __shared__ __align__(16) float Ast[GSTAGES][32][36];
    __shared__ float ssc[32];

    if (ASCALE && tid < 32) ssc[tid] = scale[(long)tid * NF_ + n];

    const bool vecN = ((N & 3) == 0);

    auto issue = [&](int stage, int cc) {
        const int k0 = cc << 5;
#pragma unroll
        for (int i = 0; i < 2; i++) {
            const int slot = tid + i * 128;
            const int m = slot >> 3, q = slot & 7;
            const int kk = k0 + q * 4;
            unsigned dst = (unsigned)__cvta_generic_to_shared(&Ast[stage][m][q * 4]);
            cpa16(dst, A + (long)m * lda + kk, kk < K);
        }
        if (vecN) {
#pragma unroll
            for (int i = 0; i < 4; i++) {
                const int slot = tid + i * 128;
                const int kr = slot >> 4, c4 = (slot & 15) * 4;
                const int kk = k0 + kr, jj = j0 + c4;
                unsigned dst = (unsigned)__cvta_generic_to_shared(&Wst[stage][kr][c4]);
                cpa16(dst, W + (long)kk * N + jj, (kk < K) && (jj < N));
            }
        } else {
#pragma unroll
            for (int i = 0; i < 16; i++) {
                const int slot = tid + i * 128;
                const int kr = slot >> 6, nn = slot & 63;
                const int kk = k0 + kr, jj = j0 + nn;
                const bool ok = (kk < K) && (jj < N);
                unsigned dst = (unsigned)__cvta_generic_to_shared(&Wst[stage][kr][nn]);
                cpa4(dst, ok ? (W + (long)kk * N + jj) : W, ok);
            }
        }
        cpa_commit();
    };

    float acc[2][2][4];
#pragma unroll
    for (int mt = 0; mt < 2; mt++)
#pragma unroll
        for (int nt = 0; nt < 2; nt++)
#pragma unroll
            for (int i = 0; i < 4; i++) acc[mt][nt][i] = 0.f;

    for (int p = 0; p < GSTAGES - 1; p++) {
        if (c0 + p < c1) issue(p, c0 + p);
        else cpa_commit();
    }

    for (int cc = c0; cc < c1; cc++) {
        cpa_wait1();
        __syncthreads();
        const int t = cc - c0;
        if (cc + GSTAGES - 1 < c1) issue((t + GSTAGES - 1) % GSTAGES, cc + GSTAGES - 1);
        else cpa_commit();

        const int s = t % GSTAGES;
        const float* Ab = &Ast[s][0][0];
        const float* Wb = &Wst[s][0][0];
#pragma unroll
        for (int kb = 0; kb < 2; kb++) {
            const int k16 = kb * 16;
            unsigned ah[2][4], al[2][4], bh[2][2], bl[2][2];
#pragma unroll
            for (int mt = 0; mt < 2; mt++) {
                const int m0 = mt * 16;
                float2 v0 = *(const float2*)(Ab + (m0 + gr) * 36 + k16 + 2 * gq);
                float2 v1 = *(const float2*)(Ab + (m0 + gr + 8) * 36 + k16 + 2 * gq);
                float2 v2 = *(const float2*)(Ab + (m0 + gr) * 36 + k16 + 8 + 2 * gq);
                float2 v3 = *(const float2*)(Ab + (m0 + gr + 8) * 36 + k16 + 8 + 2 * gq);
                if (ARELU) {
                    v0.x = fmaxf(v0.x, 0.f); v0.y = fmaxf(v0.y, 0.f);
                    v1.x = fmaxf(v1.x, 0.f); v1.y = fmaxf(v1.y, 0.f);
                    v2.x = fmaxf(v2.x, 0.f); v2.y = fmaxf(v2.y, 0.f);
                    v3.x = fmaxf(v3.x, 0.f); v3.y = fmaxf(v3.y, 0.f);
                }
                if (ASCALE) {
                    const float s0 = ssc[m0 + gr], s1 = ssc[m0 + gr + 8];
                    v0.x *= s0; v0.y *= s0; v2.x *= s0; v2.y *= s0;
                    v1.x *= s1; v1.y *= s1; v3.x *= s1; v3.y *= s1;
                }
                split2(v0.x, v0.y, ah[mt][0], al[mt][0]);
                split2(v1.x, v1.y, ah[mt][1], al[mt][1]);
                split2(v2.x, v2.y, ah[mt][2], al[mt][2]);
                split2(v3.x, v3.y, ah[mt][3], al[mt][3]);
            }
#pragma unroll
            for (int nt = 0; nt < 2; nt++) {
                const int nc = warp * 16 + nt * 8 + gr;
                float w0 = Wb[(k16 + 2 * gq) * 68 + nc];
                float w1 = Wb[(k16 + 2 * gq + 1) * 68 + nc];
                split2(w0, w1, bh[nt][0], bl[nt][0]);
                w0 = Wb[(k16 + 8 + 2 * gq) * 68 + nc];
                w1 = Wb[(k16 + 9 + 2 * gq) * 68 + nc];
                split2(w0, w1, bh[nt][1], bl[nt][1]);
            }
#pragma unroll
            for (int mt = 0; mt < 2; mt++)
#pragma unroll
                for (int nt = 0; nt < 2; nt++) {
                    mma_bf16(acc[mt][nt], ah[mt], bh[nt]);
                    mma_bf16(acc[mt][nt], al[mt], bh[nt]);
                    mma_bf16(acc[mt][nt], ah[mt], bl[nt]);
                }
        }
        __syncthreads();
    }

#pragma unroll
    for (int mt = 0; mt < 2; mt++) {
#pragma unroll
        for (int nt = 0; nt < 2; nt++) {
            const float* ac = acc[mt][nt];
            const int row0 = mt * 16 + gr;
            const int col  = j0 + warp * 16 + nt * 8 + 2 * gq;
            if (ATOMIC) {
                if (col < N) {
                    atomicAdd(&C[(long)row0 * ldc + col], ac[0]);
                    atomicAdd(&C[(long)(row0 + 8) * ldc + col], ac[2]);
                }
                if (col + 1 < N) {
                    atomicAdd(&C[(long)row0 * ldc + col + 1], ac[1]);
                    atomicAdd(&C[(long)(row0 + 8) * ldc + col + 1], ac[3]);
                }
            } else {
                const float* bn = bias + (long)n * strideBias_n;
#pragma unroll
                for (int h = 0; h < 2; h++) {
                    const int j = col + h;
                    if (j < N) {
                        float v0 = ac[h]     + bn[j];
                        float v1 = ac[h + 2] + bn[j];
                        if (ORELU) { v0 = fmaxf(v0, 0.f); v1 = fmaxf(v1, 0.f); }
                        C[(long)row0 * ldc + j] = v0;
                        C[(long)(row0 + 8) * ldc + j] = v1;
                    }
                }
            }
        }
    }
}

// ---------------- launch ----------------
extern "C" void kernel_launch(void* const* d_in, const int* in_sizes, int n_in,
                              void* d_out, int out_size)
{
    const float* x   = (const float*)d_in[0];
    const float* cw1 = (const float*)d_in[1];
    const float* cb1 = (const float*)d_in[2];
    const float* cw2 = (const float*)d_in[3];
    const float* cb2 = (const float*)d_in[4];
    const float* cw3 = (const float*)d_in[5];
    const float* cb3 = (const float*)d_in[6];
    const float* wa  = (const float*)d_in[7];
    const float* ew1 = (const float*)d_in[9];
    const float* eb1 = (const float*)d_in[10];
    const float* ew2 = (const float*)d_in[11];
    const float* eb2 = (const float*)d_in[12];
    const float* ew3 = (const float*)d_in[13];
    const float* eb3 = (const float*)d_in[14];
    const float* fw1 = (const float*)d_in[15];
    const float* fb1 = (const float*)d_in[16];
    const float* fw2 = (const float*)d_in[17];
    const float* fb2 = (const float*)d_in[18];
    const float* fw3 = (const float*)d_in[19];
    const float* fb3 = (const float*)d_in[20];
    float* out = (float*)d_out;

    float *f, *lg, *att, *h1, *h2, *e, *g1, *g2;
    unsigned *p1h, *p1l, *p2h, *p2l, *wh2, *wl2, *wh3, *wl3;
    cudaGetSymbolAddress((void**)&p1h, g_p1h);
    cudaGetSymbolAddress((void**)&p1l, g_p1l);
    cudaGetSymbolAddress((void**)&p2h, g_p2h);
    cudaGetSymbolAddress((void**)&p2l, g_p2l);
    cudaGetSymbolAddress((void**)&f,   g_f);
    cudaGetSymbolAddress((void**)&lg,  g_lg);
    cudaGetSymbolAddress((void**)&att, g_at);
    cudaGetSymbolAddress((void**)&h1,  g_h1);
    cudaGetSymbolAddress((void**)&h2,  g_h2);
    cudaGetSymbolAddress((void**)&e,   g_e);
    cudaGetSymbolAddress((void**)&g1,  g_g1);
    cudaGetSymbolAddress((void**)&g2,  g_g2);
    cudaGetSymbolAddress((void**)&wh2, g_wh2);
    cudaGetSymbolAddress((void**)&wl2, g_wl2);
    cudaGetSymbolAddress((void**)&wh3, g_wh3);
    cudaGetSymbolAddress((void**)&wl3, g_wl3);

    conv_wprep_kernel<<<36, 256>>>(cw2, wh2, wl2, 32, 64);
    conv_wprep_kernel<<<144, 256>>>(cw3, wh3, wl3, 64, 128);

    // CNN stem (pair-plane dataflow)
    conv1_kernel<<<dim3(49, 4, 32), 256>>>(x, cw1, cb1, p1h, p1l);
    conv_bf_kernel<true, false><<<dim3(7, 14, 32), 256>>>(
        p1h, p1l, wh2, wl2, cb2, nullptr, p2h, p2l, nullptr, nullptr, 112, 112, 32, 64, 1);
    zero_kernel<<<16, 256>>>(lg, 32 * 128);
    conv_bf_kernel<false, true><<<dim3(4, 7, 64), 256>>>(
        p2h, p2l, wh3, wl3, cb3, f, nullptr, nullptr, wa, lg, 56, 56, 64, 128, 2);

    attn_softmax_kernel<<<32, 128>>>(lg, att);

    // experts
    gemm_bf_kernel<false, true, false, true><<<dim3(13, 128, 1), 128>>>(
        f, 784L, 128L * 784, att, ew1, 784L * 784, eb1, 784L, h1, 784L, 128L * 784, 784, 784);
    gemm_bf_kernel<false, false, false, true><<<dim3(7, 128, 1), 128>>>(
        h1, 784L, 128L * 784, nullptr, ew2, 784L * 392, eb2, 392L, h2, 392L, 128L * 392, 784, 392);
    gemm_bf_kernel<false, false, false, true><<<dim3(1, 128, 1), 128>>>(
        h2, 392L, 128L * 392, nullptr, ew3, 392L * 64, eb3, 64L, e, 64L, 8192L, 392, 64);

    // head: f1 k-split x2 atomic (relu deferred to f2 A-load)
    init_bias_kernel<<<1024, 256>>>(g1, fb1, FIN_, B_);
    gemm_bf_kernel<false, false, true, false><<<dim3(128, 1, 2), 128>>>(
        e, 0L, 8192L, nullptr, fw1, 0L, nullptr, 0L, g1, 0L, 8192L, 8192, 8192);

    init_bias_kernel<<<512, 256>>>(g2, fb2, FHID_, B_);
    gemm_bf_kernel<true, false, true, false><<<dim3(64, 1, 2), 128>>>(
        g1, 0L, 8192L, nullptr, fw2, 0L, nullptr, 0L, g2, 0L, 4096L, 8192, 4096);

    init_bias_kernel<<<7, 256>>>(out, fb3, OUT_, B_);
    gemm_bf_kernel<true, false, true, false><<<dim3(1, 1, 16), 128>>>(
        g2, 0L, 4096L, nullptr, fw3, 0L, nullptr, 0L, out, 0L, 53L, 4096, 53);
}